// round 10
// baseline (speedup 1.0000x reference)
#include <cuda_runtime.h>
#include <math.h>

#define NN   65536
#define NG   1024
#define PIT  68

typedef unsigned long long u64;

__device__ __align__(16) float g_bufA[NN*64];
__device__ __align__(16) float g_bufB[NN*64];
__device__ __align__(16) float g_ps[64*NG];   // channel-major partial sums
__device__ __align__(16) float g_pq[64*NG];   // channel-major partial sumsq
__device__ float g_scale[5][64];
__device__ float g_shift[5][64];
__device__ int   g_ctr;

static __device__ __forceinline__ u64 f2fma(u64 a, u64 b, u64 c){
  u64 d; asm("fma.rn.f32x2 %0, %1, %2, %3;" : "=l"(d) : "l"(a), "l"(b), "l"(c)); return d;
}
static __device__ __forceinline__ u64 f2add(u64 a, u64 b){
  u64 d; asm("add.rn.f32x2 %0, %1, %2;" : "=l"(d) : "l"(a), "l"(b)); return d;
}
static __device__ __forceinline__ u64 f2mul(u64 a, u64 b){
  u64 d; asm("mul.rn.f32x2 %0, %1, %2;" : "=l"(d) : "l"(a), "l"(b)); return d;
}
static __device__ __forceinline__ u64 f2pack(float x, float y){
  u64 d; asm("mov.b64 %0, {%1,%2};" : "=l"(d) : "f"(x), "f"(y)); return d;
}
static __device__ __forceinline__ float f2lo(u64 a){ return __uint_as_float((unsigned)a); }
static __device__ __forceinline__ float f2hi(u64 a){ return __uint_as_float((unsigned)(a>>32)); }

static __device__ __forceinline__ float4 f4min(float4 a, float4 b){
  return make_float4(fminf(a.x,b.x),fminf(a.y,b.y),fminf(a.z,b.z),fminf(a.w,b.w));
}

// ---- balanced W-GEMM: out[dn+4i][cw+8r] += X[n][k].W[c][k], f32x2 over k ----
static __device__ __forceinline__ void bgemmW(u64 acc[4][4], const float* X, const float* W,
                                              int dn, int cw){
  #pragma unroll 2
  for(int ch=0;ch<16;ch++){
    ulonglong2 xv[4], wv[4];
    #pragma unroll
    for(int i=0;i<4;i++) xv[i] = *(const ulonglong2*)(X + (dn+4*i)*PIT + 4*ch);
    #pragma unroll
    for(int r=0;r<4;r++) wv[r] = *(const ulonglong2*)(W + (cw+8*r)*PIT + 4*ch);
    #pragma unroll
    for(int i=0;i<4;i++)
      #pragma unroll
      for(int r=0;r<4;r++){
        acc[i][r]=f2fma(xv[i].x, wv[r].x, acc[i][r]);
        acc[i][r]=f2fma(xv[i].y, wv[r].y, acc[i][r]);
      }
  }
}

// ---- balanced S-GEMM: out[dn+4i][cs..cs+3] += S[d][s].X[s][c], f32x2 over c ----
static __device__ __forceinline__ void bgemmS(u64 acc[4][2], const float* S, const float* X,
                                              int dn, int cs){
  #pragma unroll 2
  for(int sc=0;sc<16;sc++){
    float av[4][4]; ulonglong2 bv[4];
    #pragma unroll
    for(int i=0;i<4;i++) *(float4*)av[i] = *(const float4*)(S + (dn+4*i)*PIT + 4*sc);
    #pragma unroll
    for(int u=0;u<4;u++) bv[u] = *(const ulonglong2*)(X + (4*sc+u)*PIT + cs);
    #pragma unroll
    for(int i=0;i<4;i++)
      #pragma unroll
      for(int u=0;u<4;u++){
        u64 p = f2pack(av[i][u], av[i][u]);
        acc[i][0]=f2fma(p, bv[u].x, acc[i][0]);
        acc[i][1]=f2fma(p, bv[u].y, acc[i][1]);
      }
  }
}

// ---- per-CTA stats (all 256 threads) + last-CTA BN finalize ----
// pp/qq: 512 floats of free smem. Must be called by all 256 threads.
static __device__ __forceinline__ void stats_finalize(const float* ys, float* pp, float* qq,
                                                      int g, int t,
                                                      const float* __restrict__ gam,
                                                      const float* __restrict__ bet, int si){
  const int c = t & 63, qu = t >> 6;
  float s = 0.f, s2 = 0.f;
  #pragma unroll
  for(int k=0;k<16;k++){
    float v = ys[(qu*16+k)*PIT + c];
    s += v; s2 += v*v;
  }
  pp[qu*64+c] = s; qq[qu*64+c] = s2;
  __syncthreads();
  if(t < 64){
    float a  = pp[t]+pp[t+64]+pp[t+128]+pp[t+192];
    float b2 = qq[t]+qq[t+64]+qq[t+128]+qq[t+192];
    g_ps[t*NG+g] = a; g_pq[t*NG+g] = b2;
    __threadfence();
  }
  __shared__ unsigned rdone;
  __syncthreads();
  if(t == 0) rdone = (unsigned)atomicAdd(&g_ctr, 1);
  __syncthreads();
  if(rdone == NG-1){
    const int cc = t>>2, sub = t&3;
    const float4* P = (const float4*)(g_ps + cc*NG + sub*256);
    const float4* Q = (const float4*)(g_pq + cc*NG + sub*256);
    float s1 = 0.f, sq = 0.f;
    #pragma unroll 8
    for(int i=0;i<64;i++){
      float4 a = __ldcg(P+i); s1 += a.x+a.y+a.z+a.w;
      float4 b = __ldcg(Q+i); sq += b.x+b.y+b.z+b.w;
    }
    s1 += __shfl_xor_sync(0xffffffffu, s1, 1); sq += __shfl_xor_sync(0xffffffffu, sq, 1);
    s1 += __shfl_xor_sync(0xffffffffu, s1, 2); sq += __shfl_xor_sync(0xffffffffu, sq, 2);
    if(sub == 0){
      float mu  = s1*(1.f/(float)NN);
      float var = sq*(1.f/(float)NN) - mu*mu;
      float sc  = __ldg(gam+cc) * rsqrtf(var + 1e-5f);
      g_scale[si][cc] = sc; g_shift[si][cc] = __ldg(bet+cc) - mu*sc;
    }
    if(t == 0) g_ctr = 0;
  }
}

// =============== cheb layer 1: feat (N,16) -> pre-BN (N,64) ===============
__global__ __launch_bounds__(256,3) void k_cheb1(const float* __restrict__ feat,
                                                 const int* __restrict__ src,
                                                 const float* __restrict__ w,
                                                 const float* __restrict__ b,
                                                 const float* __restrict__ gam,
                                                 const float* __restrict__ bet){
  extern __shared__ float sm[];
  float* xs = sm;            // 64*20
  float* x1 = sm + 1280;
  float* x2 = sm + 2560;
  float* wt = sm + 3840;     // 64 rows pitch 52 (free after GEMM)
  float* ys = sm + 7168;     // 64*68
  unsigned char* ls = (unsigned char*)(sm + 11520);
  const int g = blockIdx.x, t = threadIdx.x;

  for(int i=t;i<768;i+=256){
    int h = i & 63, kq = i >> 6;
    *(float4*)(wt + h*52 + 4*kq) = __ldg((const float4*)(w + h*48) + kq);
  }
  for(int i=t;i<256;i+=256){
    int nn = i>>2, j = i&3;
    *(float4*)(xs + nn*20 + 4*j) = __ldg((const float4*)(feat + (g*64+nn)*16) + j);
  }
  for(int i=t;i<1024;i+=256) ls[i] = (unsigned char)(__ldg(src + g*1024 + i) & 63);
  __syncthreads();

  const int n = t>>2, q = t&3, c0 = 4*q;
  const unsigned char* lr = ls + n*16;
  const u64 cm16 = f2pack(-0.0625f,-0.0625f);
  const u64 c125 = f2pack(0.125f,0.125f);
  const u64 cm1  = f2pack(-1.f,-1.f);
  { u64 A0=0,A1=0;
    #pragma unroll
    for(int j=0;j<16;j++){
      ulonglong2 r = *(const ulonglong2*)(xs + (int)lr[j]*20 + c0);
      A0 = f2add(A0, r.x); A1 = f2add(A1, r.y);
    }
    ulonglong2 o; o.x = f2mul(A0, cm16); o.y = f2mul(A1, cm16);
    *(ulonglong2*)(x1 + n*20 + c0) = o; }
  __syncthreads();
  { u64 A0=0,A1=0;
    #pragma unroll
    for(int j=0;j<16;j++){
      ulonglong2 r = *(const ulonglong2*)(x1 + (int)lr[j]*20 + c0);
      A0 = f2add(A0, r.x); A1 = f2add(A1, r.y);
    }
    ulonglong2 X0 = *(const ulonglong2*)(xs + n*20 + c0);
    ulonglong2 o;
    o.x = f2mul(f2fma(A0, c125, X0.x), cm1);
    o.y = f2mul(f2fma(A1, c125, X0.y), cm1);
    *(ulonglong2*)(x2 + n*20 + c0) = o; }
  __syncthreads();

  const int c4 = t & 15, n0 = (t>>4)*4;
  u64 acc[4][4];
  #pragma unroll
  for(int i=0;i<4;i++)
    #pragma unroll
    for(int j=0;j<4;j++) acc[i][j] = 0ull;
  const float* bufs[3] = {xs, x1, x2};
  #pragma unroll
  for(int seg=0;seg<3;seg++){
    const float* X = bufs[seg];
    #pragma unroll
    for(int ch=0;ch<4;ch++){
      ulonglong2 xv[4];
      #pragma unroll
      for(int i=0;i<4;i++) xv[i] = *(const ulonglong2*)(X + (n0+i)*20 + 4*ch);
      #pragma unroll
      for(int j=0;j<4;j++){
        ulonglong2 wv = *(const ulonglong2*)(wt + (c4+16*j)*52 + seg*16 + 4*ch);
        #pragma unroll
        for(int i=0;i<4;i++){
          acc[i][j] = f2fma(xv[i].x, wv.x, acc[i][j]);
          acc[i][j] = f2fma(xv[i].y, wv.y, acc[i][j]);
        }
      }
    }
  }
  __syncthreads();
  float bj[4];
  #pragma unroll
  for(int j=0;j<4;j++) bj[j] = __ldg(b + c4 + 16*j);
  float* obase = g_bufA + (g*64+n0)*64;
  #pragma unroll
  for(int i=0;i<4;i++)
    #pragma unroll
    for(int j=0;j<4;j++){
      float v = f2lo(acc[i][j]) + f2hi(acc[i][j]) + bj[j];
      ys[(n0+i)*PIT + c4 + 16*j] = v;
      obase[i*64 + c4 + 16*j] = v;
    }
  __syncthreads();
  stats_finalize(ys, wt, wt+256, g, t, gam, bet, 0);
}

// =============== cheb layers 2/3: laps as S-GEMMs ===============
// floats: xs 0  x1 4352  S 8704  wt 13056  scs 17408 shs 17472
__global__ __launch_bounds__(256,3) void k_chebH(const float* __restrict__ w,
                                                 const float* __restrict__ b,
                                                 int si, int so,
                                                 const float* __restrict__ gam,
                                                 const float* __restrict__ bet,
                                                 const int* __restrict__ src,
                                                 const float* __restrict__ in,
                                                 float* __restrict__ out){
  extern __shared__ float sm[];
  float* xs  = sm;
  float* x1  = sm + 4352;
  float* S   = sm + 8704;
  float* wt  = sm + 13056;
  float* scs = sm + 17408;
  float* shs = sm + 17472;
  float* ys  = x1;
  const int g = blockIdx.x, t = threadIdx.x;
  const int lane = t & 31, wp = t >> 5;
  const int dn = (wp>>1)*16 + (lane>>3);
  const int cs = (wp&1)*32 + (lane&7)*4;
  const int cw = (wp&1)*32 + (lane&7);

  if(t < 64){ scs[t] = g_scale[si][t]; shs[t] = g_shift[si][t]; }
  { float4 z = make_float4(0.f,0.f,0.f,0.f);
    for(int i=t;i<1088;i+=256) ((float4*)S)[i] = z; }
  for(int i=t;i<1024;i+=256){
    int nn=i>>4, j=i&15;
    *(float4*)(xs + nn*PIT + 4*j) = __ldg((const float4*)(in + (g*64+nn)*64) + j);
  }
  for(int i=t;i<1024;i+=256){
    int h=i&63, kq=i>>6;
    *(float4*)(wt + h*PIT + 4*kq) = __ldg((const float4*)(w + h*192) + kq);
  }
  __syncthreads();
  for(int i=t;i<1024;i+=256){
    int nn=i>>4, j=i&15, c=4*j;
    float4 v = *(float4*)(xs + nn*PIT + c);
    v.x=fmaxf(fmaf(v.x,scs[c+0],shs[c+0]),0.f);
    v.y=fmaxf(fmaf(v.y,scs[c+1],shs[c+1]),0.f);
    v.z=fmaxf(fmaf(v.z,scs[c+2],shs[c+2]),0.f);
    v.w=fmaxf(fmaf(v.w,scs[c+3],shs[c+3]),0.f);
    *(float4*)(xs + nn*PIT + c) = v;
  }
  for(int i=t;i<1024;i+=256){
    int sl = __ldg(src + g*1024 + i) & 63;
    atomicAdd(S + (i>>4)*PIT + sl, -0.0625f);
  }
  __syncthreads();

  u64 aW[4][4];
  #pragma unroll
  for(int i=0;i<4;i++)
    #pragma unroll
    for(int r=0;r<4;r++) aW[i][r] = 0ull;

  bgemmW(aW, xs, wt, dn, cw);
  { u64 aS[4][2] = {{0,0},{0,0},{0,0},{0,0}};
    bgemmS(aS, S, xs, dn, cs);
    #pragma unroll
    for(int i=0;i<4;i++){
      ulonglong2 o; o.x = aS[i][0]; o.y = aS[i][1];
      *(ulonglong2*)(x1 + (dn+4*i)*PIT + cs) = o;
    }
  }
  __syncthreads();
  for(int i=t;i<1024;i+=256){
    int h=i&63, kq=i>>6;
    *(float4*)(wt + h*PIT + 4*kq) = __ldg((const float4*)(w + h*192) + 16 + kq);
  }
  __syncthreads();
  bgemmW(aW, x1, wt, dn, cw);
  { u64 aS[4][2] = {{0,0},{0,0},{0,0},{0,0}};
    bgemmS(aS, S, x1, dn, cs);
    const u64 two = f2pack(2.f,2.f), mone = f2pack(-1.f,-1.f);
    #pragma unroll
    for(int i=0;i<4;i++){
      ulonglong2 x0 = *(const ulonglong2*)(xs + (dn+4*i)*PIT + cs);
      ulonglong2 o;
      o.x = f2fma(two, aS[i][0], f2mul(x0.x, mone));
      o.y = f2fma(two, aS[i][1], f2mul(x0.y, mone));
      *(ulonglong2*)(xs + (dn+4*i)*PIT + cs) = o;
    }
  }
  __syncthreads();
  for(int i=t;i<1024;i+=256){
    int h=i&63, kq=i>>6;
    *(float4*)(wt + h*PIT + 4*kq) = __ldg((const float4*)(w + h*192) + 32 + kq);
  }
  __syncthreads();
  bgemmW(aW, xs, wt, dn, cw);
  __syncthreads();   // wt reads done (free for stats); x1 reads done -> ys writable
  { float bj[4];
    #pragma unroll
    for(int r=0;r<4;r++) bj[r] = __ldg(b + cw + 8*r);
    #pragma unroll
    for(int i=0;i<4;i++)
      #pragma unroll
      for(int r=0;r<4;r++)
        ys[(dn+4*i)*PIT + cw + 8*r] = f2lo(aW[i][r]) + f2hi(aW[i][r]) + bj[r];
  }
  __syncthreads();
  for(int i=t;i<1024;i+=256){
    int nn=i>>4, j=i&15;
    *(float4*)(out + (g*64+nn)*64 + 4*j) = *(const float4*)(ys + nn*PIT + 4*j);
  }
  stats_finalize(ys, wt, wt+256, g, t, gam, bet, so);
}

// =============== edge conv: balanced GEMMs, gather-min ===============
__global__ __launch_bounds__(256,3) void k_econv(const float* __restrict__ tw,
                                                 const float* __restrict__ tb,
                                                 const float* __restrict__ pw,
                                                 const float* __restrict__ pb,
                                                 int si, int so,
                                                 const float* __restrict__ gam,
                                                 const float* __restrict__ bet,
                                                 const int* __restrict__ src,
                                                 const float* __restrict__ in,
                                                 float* __restrict__ out){
  extern __shared__ float sm[];
  float* xs  = sm;          float* psum = sm;
  float* wA  = sm + 4352;   float* ys   = sm + 4352;
  float* wB  = sm + 8704;   // free after pass 2 -> stats scratch
  float* ts  = sm + 13056;
  float* scs = sm + 17408;
  float* shs = sm + 17472;
  float* cbs = sm + 17536;
  unsigned char* ls = (unsigned char*)(sm + 17600);
  const int g = blockIdx.x, t = threadIdx.x;
  const int lane = t & 31, wp = t >> 5;
  const int dn = (wp>>1)*16 + (lane>>3);
  const int cw = (wp&1)*32 + (lane&7);

  if(t < 64){
    scs[t]=g_scale[si][t]; shs[t]=g_shift[si][t];
    cbs[t]=__ldg(tb+t)+__ldg(pb+t);
  }
  for(int i=t;i<1024;i+=256){
    int h = i & 63, kq = i >> 6;
    *(float4*)(wA + h*PIT + 4*kq) = __ldg((const float4*)(tw + h*64) + kq);
    *(float4*)(wB + h*PIT + 4*kq) = __ldg((const float4*)(pw + h*64) + kq);
  }
  for(int i=t;i<1024;i+=256) ls[i] = (unsigned char)(__ldg(src + g*1024 + i) & 63);
  for(int i=t;i<1024;i+=256){
    int nn=i>>4, j=i&15;
    *(float4*)(xs + nn*PIT + 4*j) = __ldg((const float4*)(in + (g*64+nn)*64) + j);
  }
  __syncthreads();
  for(int i=t;i<1024;i+=256){
    int nn=i>>4, j=i&15, c=4*j;
    float4 v = *(float4*)(xs + nn*PIT + c);
    v.x=fmaxf(fmaf(v.x,scs[c+0],shs[c+0]),0.f);
    v.y=fmaxf(fmaf(v.y,scs[c+1],shs[c+1]),0.f);
    v.z=fmaxf(fmaf(v.z,scs[c+2],shs[c+2]),0.f);
    v.w=fmaxf(fmaf(v.w,scs[c+3],shs[c+3]),0.f);
    *(float4*)(xs + nn*PIT + c) = v;
  }
  __syncthreads();

  { u64 ta[4][4];
    #pragma unroll
    for(int i=0;i<4;i++)
      #pragma unroll
      for(int r=0;r<4;r++) ta[i][r]=0ull;
    bgemmW(ta, xs, wA, dn, cw);
    #pragma unroll
    for(int i=0;i<4;i++)
      #pragma unroll
      for(int r=0;r<4;r++)
        ts[(dn+4*i)*PIT + cw + 8*r] = f2lo(ta[i][r]) + f2hi(ta[i][r]);
  }
  u64 pa[4][4];
  #pragma unroll
  for(int i=0;i<4;i++)
    #pragma unroll
    for(int r=0;r<4;r++) pa[i][r]=0ull;
  bgemmW(pa, xs, wB, dn, cw);
  __syncthreads();
  #pragma unroll
  for(int i=0;i<4;i++)
    #pragma unroll
    for(int r=0;r<4;r++){
      int c = cw + 8*r, d = dn + 4*i;
      psum[d*PIT + c] = ts[d*PIT + c] + f2lo(pa[i][r]) + f2hi(pa[i][r]) + cbs[c];
    }
  __syncthreads();

  const int n = t>>2, q = t&3, c0 = q*16;
  const unsigned char* lr = ls + n*16;
  float4 mn[4];
  #pragma unroll
  for(int m=0;m<4;m++) mn[m]=make_float4(3e38f,3e38f,3e38f,3e38f);
  #pragma unroll
  for(int j=0;j<16;j++){
    const float4* r = (const float4*)(ts + (int)lr[j]*PIT + c0);
    #pragma unroll
    for(int m=0;m<4;m++) mn[m] = f4min(mn[m], r[m]);
  }
  float* orow = out + (g*64+n)*64;
  #pragma unroll
  for(int m=0;m<4;m++){
    float4 p = *(const float4*)(psum + n*PIT + c0 + 4*m);
    float4 ov = make_float4(p.x-mn[m].x, p.y-mn[m].y, p.z-mn[m].z, p.w-mn[m].w);
    *(float4*)(ys + n*PIT + c0 + 4*m) = ov;
    *(float4*)(orow + c0 + 4*m) = ov;
  }
  __syncthreads();
  stats_finalize(ys, wB, wB+256, g, t, gam, bet, so);
}

// ---------- final BN+ReLU + mean pool (coalesced) ----------
__global__ __launch_bounds__(256) void k_pool(const float* __restrict__ in,
                                              float* __restrict__ out){
  __shared__ float sp[1024];
  const int g = blockIdx.x, t = threadIdx.x;
  const int j = t & 15, row0 = t >> 4, c0 = 4*j;
  float sc0=g_scale[4][c0+0], sc1=g_scale[4][c0+1], sc2=g_scale[4][c0+2], sc3=g_scale[4][c0+3];
  float sh0=g_shift[4][c0+0], sh1=g_shift[4][c0+1], sh2=g_shift[4][c0+2], sh3=g_shift[4][c0+3];
  float4 acc = make_float4(0.f,0.f,0.f,0.f);
  #pragma unroll
  for(int r=0;r<4;r++){
    int nn = row0 + 16*r;
    float4 v = __ldg((const float4*)(in + (g*64+nn)*64 + c0));
    acc.x += fmaxf(fmaf(v.x,sc0,sh0),0.f);
    acc.y += fmaxf(fmaf(v.y,sc1,sh1),0.f);
    acc.z += fmaxf(fmaf(v.z,sc2,sh2),0.f);
    acc.w += fmaxf(fmaf(v.w,sc3,sh3),0.f);
  }
  *(float4*)(sp + row0*64 + c0) = acc;
  __syncthreads();
  if(t < 64){
    float s = 0.f;
    #pragma unroll
    for(int k=0;k<16;k++) s += sp[k*64 + t];
    out[g*64 + t] = s*(1.f/64.f);
  }
}

extern "C" void kernel_launch(void* const* d_in, const int* in_sizes, int n_in,
                              void* d_out, int out_size){
  const float* feat = (const float*)d_in[0];
  const int*   src  = (const int*)d_in[1];
  const float *c1w=(const float*)d_in[4],  *c1b=(const float*)d_in[5];
  const float *bn1g=(const float*)d_in[6], *bn1b=(const float*)d_in[7];
  const float *e1tw=(const float*)d_in[8], *e1tb=(const float*)d_in[9];
  const float *e1pw=(const float*)d_in[10],*e1pb=(const float*)d_in[11];
  const float *bne1g=(const float*)d_in[12],*bne1b=(const float*)d_in[13];
  const float *c2w=(const float*)d_in[14], *c2b=(const float*)d_in[15];
  const float *bn2g=(const float*)d_in[16],*bn2b=(const float*)d_in[17];
  const float *e2tw=(const float*)d_in[18],*e2tb=(const float*)d_in[19];
  const float *e2pw=(const float*)d_in[20],*e2pb=(const float*)d_in[21];
  const float *bne2g=(const float*)d_in[22],*bne2b=(const float*)d_in[23];
  const float *c3w=(const float*)d_in[24], *c3b=(const float*)d_in[25];
  const float *bn3g=(const float*)d_in[26],*bn3b=(const float*)d_in[27];
  float* out = (float*)d_out;

  const int SM1 = 11776*4;
  const int SMH = 17544*4;
  const int SME = 17864*4;
  cudaFuncSetAttribute(k_cheb1, cudaFuncAttributeMaxDynamicSharedMemorySize, SM1);
  cudaFuncSetAttribute(k_chebH, cudaFuncAttributeMaxDynamicSharedMemorySize, SMH);
  cudaFuncSetAttribute(k_econv, cudaFuncAttributeMaxDynamicSharedMemorySize, SME);

  float *bufA, *bufB;
  cudaGetSymbolAddress((void**)&bufA, g_bufA);
  cudaGetSymbolAddress((void**)&bufB, g_bufB);

  k_cheb1<<<NG, 256, SM1>>>(feat, src, c1w, c1b, bn1g, bn1b);
  k_econv<<<NG, 256, SME>>>(e1tw, e1tb, e1pw, e1pb, 0, 1, bne1g, bne1b, src, bufA, bufB);
  k_chebH<<<NG, 256, SMH>>>(c2w, c2b, 1, 2, bn2g, bn2b, src, bufB, bufA);
  k_econv<<<NG, 256, SME>>>(e2tw, e2tb, e2pw, e2pb, 2, 3, bne2g, bne2b, src, bufA, bufB);
  k_chebH<<<NG, 256, SMH>>>(c3w, c3b, 3, 4, bn3g, bn3b, src, bufB, bufA);
  k_pool<<<NG, 256>>>(bufA, out);
}

// round 11
// speedup vs baseline: 2.2304x; 2.2304x over previous
#include <cuda_runtime.h>
#include <math.h>

#define NN   65536
#define NG   1024
#define PIT  68

typedef unsigned long long u64;

__device__ __align__(16) float g_bufA[NN*64];
__device__ __align__(16) float g_bufB[NN*64];
__device__ __align__(16) float g_ps[64*NG];   // channel-major partial sums
__device__ __align__(16) float g_pq[64*NG];   // channel-major partial sumsq
__device__ float g_scale[5][64];
__device__ float g_shift[5][64];

static __device__ __forceinline__ u64 f2fma(u64 a, u64 b, u64 c){
  u64 d; asm("fma.rn.f32x2 %0, %1, %2, %3;" : "=l"(d) : "l"(a), "l"(b), "l"(c)); return d;
}
static __device__ __forceinline__ u64 f2add(u64 a, u64 b){
  u64 d; asm("add.rn.f32x2 %0, %1, %2;" : "=l"(d) : "l"(a), "l"(b)); return d;
}
static __device__ __forceinline__ u64 f2mul(u64 a, u64 b){
  u64 d; asm("mul.rn.f32x2 %0, %1, %2;" : "=l"(d) : "l"(a), "l"(b)); return d;
}
static __device__ __forceinline__ u64 f2pack(float x, float y){
  u64 d; asm("mov.b64 %0, {%1,%2};" : "=l"(d) : "f"(x), "f"(y)); return d;
}
static __device__ __forceinline__ float f2lo(u64 a){ return __uint_as_float((unsigned)a); }
static __device__ __forceinline__ float f2hi(u64 a){ return __uint_as_float((unsigned)(a>>32)); }

static __device__ __forceinline__ float4 f4min(float4 a, float4 b){
  return make_float4(fminf(a.x,b.x),fminf(a.y,b.y),fminf(a.z,b.z),fminf(a.w,b.w));
}

// ---- balanced W-GEMM: out[dn+4i][cw+8r] += X[n][k].W[c][k], f32x2 over k ----
static __device__ __forceinline__ void bgemmW(u64 acc[4][4], const float* X, const float* W,
                                              int dn, int cw){
  #pragma unroll 2
  for(int ch=0;ch<16;ch++){
    ulonglong2 xv[4], wv[4];
    #pragma unroll
    for(int i=0;i<4;i++) xv[i] = *(const ulonglong2*)(X + (dn+4*i)*PIT + 4*ch);
    #pragma unroll
    for(int r=0;r<4;r++) wv[r] = *(const ulonglong2*)(W + (cw+8*r)*PIT + 4*ch);
    #pragma unroll
    for(int i=0;i<4;i++)
      #pragma unroll
      for(int r=0;r<4;r++){
        acc[i][r]=f2fma(xv[i].x, wv[r].x, acc[i][r]);
        acc[i][r]=f2fma(xv[i].y, wv[r].y, acc[i][r]);
      }
  }
}

// ---- balanced S-GEMM: out[dn+4i][cs..cs+3] += S[d][s].X[s][c], f32x2 over c ----
static __device__ __forceinline__ void bgemmS(u64 acc[4][2], const float* S, const float* X,
                                              int dn, int cs){
  #pragma unroll 2
  for(int sc=0;sc<16;sc++){
    float av[4][4]; ulonglong2 bv[4];
    #pragma unroll
    for(int i=0;i<4;i++) *(float4*)av[i] = *(const float4*)(S + (dn+4*i)*PIT + 4*sc);
    #pragma unroll
    for(int u=0;u<4;u++) bv[u] = *(const ulonglong2*)(X + (4*sc+u)*PIT + cs);
    #pragma unroll
    for(int i=0;i<4;i++)
      #pragma unroll
      for(int u=0;u<4;u++){
        u64 p = f2pack(av[i][u], av[i][u]);
        acc[i][0]=f2fma(p, bv[u].x, acc[i][0]);
        acc[i][1]=f2fma(p, bv[u].y, acc[i][1]);
      }
  }
}

// ---- per-CTA stats: 256 threads, channel-major global partials ----
static __device__ __forceinline__ void stats_store(const float* ys, float* pp, float* qq,
                                                   int g, int t){
  const int c = t & 63, qu = t >> 6;
  float s = 0.f, s2 = 0.f;
  #pragma unroll
  for(int k=0;k<16;k++){
    float v = ys[(qu*16+k)*PIT + c];
    s += v; s2 += v*v;
  }
  pp[qu*64+c] = s; qq[qu*64+c] = s2;
  __syncthreads();
  if(t < 64){
    g_ps[t*NG+g] = pp[t]+pp[t+64]+pp[t+128]+pp[t+192];
    g_pq[t*NG+g] = qq[t]+qq[t+64]+qq[t+128]+qq[t+192];
  }
}

// =============== cheb layer 1: feat (N,16) -> pre-BN (N,64) ===============
__global__ __launch_bounds__(256,3) void k_cheb1(const float* __restrict__ feat,
                                                 const int* __restrict__ src,
                                                 const float* __restrict__ w,
                                                 const float* __restrict__ b){
  extern __shared__ float sm[];
  float* xs = sm;            // 64*20
  float* x1 = sm + 1280;
  float* x2 = sm + 2560;
  float* wt = sm + 3840;     // pitch 52; free after GEMM -> stats scratch
  float* ys = sm + 7168;     // 64*68
  unsigned char* ls = (unsigned char*)(sm + 11520);
  const int g = blockIdx.x, t = threadIdx.x;

  for(int i=t;i<768;i+=256){
    int h = i & 63, kq = i >> 6;
    *(float4*)(wt + h*52 + 4*kq) = __ldg((const float4*)(w + h*48) + kq);
  }
  for(int i=t;i<256;i+=256){
    int nn = i>>2, j = i&3;
    *(float4*)(xs + nn*20 + 4*j) = __ldg((const float4*)(feat + (g*64+nn)*16) + j);
  }
  for(int i=t;i<1024;i+=256) ls[i] = (unsigned char)(__ldg(src + g*1024 + i) & 63);
  __syncthreads();

  const int n = t>>2, q = t&3, c0 = 4*q;
  const unsigned char* lr = ls + n*16;
  const u64 cm16 = f2pack(-0.0625f,-0.0625f);
  const u64 c125 = f2pack(0.125f,0.125f);
  const u64 cm1  = f2pack(-1.f,-1.f);
  { u64 A0=0,A1=0;
    #pragma unroll
    for(int j=0;j<16;j++){
      ulonglong2 r = *(const ulonglong2*)(xs + (int)lr[j]*20 + c0);
      A0 = f2add(A0, r.x); A1 = f2add(A1, r.y);
    }
    ulonglong2 o; o.x = f2mul(A0, cm16); o.y = f2mul(A1, cm16);
    *(ulonglong2*)(x1 + n*20 + c0) = o; }
  __syncthreads();
  { u64 A0=0,A1=0;
    #pragma unroll
    for(int j=0;j<16;j++){
      ulonglong2 r = *(const ulonglong2*)(x1 + (int)lr[j]*20 + c0);
      A0 = f2add(A0, r.x); A1 = f2add(A1, r.y);
    }
    ulonglong2 X0 = *(const ulonglong2*)(xs + n*20 + c0);
    ulonglong2 o;
    o.x = f2mul(f2fma(A0, c125, X0.x), cm1);
    o.y = f2mul(f2fma(A1, c125, X0.y), cm1);
    *(ulonglong2*)(x2 + n*20 + c0) = o; }
  __syncthreads();

  const int c4 = t & 15, n0 = (t>>4)*4;
  u64 acc[4][4];
  #pragma unroll
  for(int i=0;i<4;i++)
    #pragma unroll
    for(int j=0;j<4;j++) acc[i][j] = 0ull;
  const float* bufs[3] = {xs, x1, x2};
  #pragma unroll
  for(int seg=0;seg<3;seg++){
    const float* X = bufs[seg];
    #pragma unroll
    for(int ch=0;ch<4;ch++){
      ulonglong2 xv[4];
      #pragma unroll
      for(int i=0;i<4;i++) xv[i] = *(const ulonglong2*)(X + (n0+i)*20 + 4*ch);
      #pragma unroll
      for(int j=0;j<4;j++){
        ulonglong2 wv = *(const ulonglong2*)(wt + (c4+16*j)*52 + seg*16 + 4*ch);
        #pragma unroll
        for(int i=0;i<4;i++){
          acc[i][j] = f2fma(xv[i].x, wv.x, acc[i][j]);
          acc[i][j] = f2fma(xv[i].y, wv.y, acc[i][j]);
        }
      }
    }
  }
  __syncthreads();
  float bj[4];
  #pragma unroll
  for(int j=0;j<4;j++) bj[j] = __ldg(b + c4 + 16*j);
  float* obase = g_bufA + (g*64+n0)*64;
  #pragma unroll
  for(int i=0;i<4;i++)
    #pragma unroll
    for(int j=0;j<4;j++){
      float v = f2lo(acc[i][j]) + f2hi(acc[i][j]) + bj[j];
      ys[(n0+i)*PIT + c4 + 16*j] = v;
      obase[i*64 + c4 + 16*j] = v;
    }
  __syncthreads();
  stats_store(ys, wt, wt+256, g, t);
}

// =============== cheb layers 2/3: laps as S-GEMMs ===============
__global__ __launch_bounds__(256,3) void k_chebH(const float* __restrict__ w,
                                                 const float* __restrict__ b,
                                                 int si, const int* __restrict__ src,
                                                 const float* __restrict__ in,
                                                 float* __restrict__ out){
  extern __shared__ float sm[];
  float* xs  = sm;
  float* x1  = sm + 4352;
  float* S   = sm + 8704;
  float* wt  = sm + 13056;
  float* scs = sm + 17408;
  float* shs = sm + 17472;
  float* ys  = x1;
  const int g = blockIdx.x, t = threadIdx.x;
  const int lane = t & 31, wp = t >> 5;
  const int dn = (wp>>1)*16 + (lane>>3);
  const int cs = (wp&1)*32 + (lane&7)*4;
  const int cw = (wp&1)*32 + (lane&7);

  if(t < 64){ scs[t] = g_scale[si][t]; shs[t] = g_shift[si][t]; }
  { float4 z = make_float4(0.f,0.f,0.f,0.f);
    for(int i=t;i<1088;i+=256) ((float4*)S)[i] = z; }
  for(int i=t;i<1024;i+=256){
    int nn=i>>4, j=i&15;
    *(float4*)(xs + nn*PIT + 4*j) = __ldg((const float4*)(in + (g*64+nn)*64) + j);
  }
  for(int i=t;i<1024;i+=256){
    int h=i&63, kq=i>>6;
    *(float4*)(wt + h*PIT + 4*kq) = __ldg((const float4*)(w + h*192) + kq);
  }
  __syncthreads();
  for(int i=t;i<1024;i+=256){
    int nn=i>>4, j=i&15, c=4*j;
    float4 v = *(float4*)(xs + nn*PIT + c);
    v.x=fmaxf(fmaf(v.x,scs[c+0],shs[c+0]),0.f);
    v.y=fmaxf(fmaf(v.y,scs[c+1],shs[c+1]),0.f);
    v.z=fmaxf(fmaf(v.z,scs[c+2],shs[c+2]),0.f);
    v.w=fmaxf(fmaf(v.w,scs[c+3],shs[c+3]),0.f);
    *(float4*)(xs + nn*PIT + c) = v;
  }
  for(int i=t;i<1024;i+=256){
    int sl = __ldg(src + g*1024 + i) & 63;
    atomicAdd(S + (i>>4)*PIT + sl, -0.0625f);
  }
  __syncthreads();

  u64 aW[4][4];
  #pragma unroll
  for(int i=0;i<4;i++)
    #pragma unroll
    for(int r=0;r<4;r++) aW[i][r] = 0ull;

  bgemmW(aW, xs, wt, dn, cw);
  { u64 aS[4][2] = {{0,0},{0,0},{0,0},{0,0}};
    bgemmS(aS, S, xs, dn, cs);
    #pragma unroll
    for(int i=0;i<4;i++){
      ulonglong2 o; o.x = aS[i][0]; o.y = aS[i][1];
      *(ulonglong2*)(x1 + (dn+4*i)*PIT + cs) = o;
    }
  }
  __syncthreads();
  for(int i=t;i<1024;i+=256){
    int h=i&63, kq=i>>6;
    *(float4*)(wt + h*PIT + 4*kq) = __ldg((const float4*)(w + h*192) + 16 + kq);
  }
  __syncthreads();
  bgemmW(aW, x1, wt, dn, cw);
  { u64 aS[4][2] = {{0,0},{0,0},{0,0},{0,0}};
    bgemmS(aS, S, x1, dn, cs);
    const u64 two = f2pack(2.f,2.f), mone = f2pack(-1.f,-1.f);
    #pragma unroll
    for(int i=0;i<4;i++){
      ulonglong2 x0 = *(const ulonglong2*)(xs + (dn+4*i)*PIT + cs);
      ulonglong2 o;
      o.x = f2fma(two, aS[i][0], f2mul(x0.x, mone));
      o.y = f2fma(two, aS[i][1], f2mul(x0.y, mone));
      *(ulonglong2*)(xs + (dn+4*i)*PIT + cs) = o;
    }
  }
  __syncthreads();
  for(int i=t;i<1024;i+=256){
    int h=i&63, kq=i>>6;
    *(float4*)(wt + h*PIT + 4*kq) = __ldg((const float4*)(w + h*192) + 32 + kq);
  }
  __syncthreads();
  bgemmW(aW, xs, wt, dn, cw);
  __syncthreads();           // wt free; x1 (=ys) writable
  { float bj[4];
    #pragma unroll
    for(int r=0;r<4;r++) bj[r] = __ldg(b + cw + 8*r);
    #pragma unroll
    for(int i=0;i<4;i++)
      #pragma unroll
      for(int r=0;r<4;r++)
        ys[(dn+4*i)*PIT + cw + 8*r] = f2lo(aW[i][r]) + f2hi(aW[i][r]) + bj[r];
  }
  __syncthreads();
  for(int i=t;i<1024;i+=256){
    int nn=i>>4, j=i&15;
    *(float4*)(out + (g*64+nn)*64 + 4*j) = *(const float4*)(ys + nn*PIT + 4*j);
  }
  stats_store(ys, wt, wt+256, g, t);
}

// =============== edge conv: balanced GEMMs, gather-min ===============
__global__ __launch_bounds__(256,3) void k_econv(const float* __restrict__ tw,
                                                 const float* __restrict__ tb,
                                                 const float* __restrict__ pw,
                                                 const float* __restrict__ pb,
                                                 int si, const int* __restrict__ src,
                                                 const float* __restrict__ in,
                                                 float* __restrict__ out){
  extern __shared__ float sm[];
  float* xs  = sm;          float* psum = sm;
  float* wA  = sm + 4352;   float* ys   = sm + 4352;
  float* wB  = sm + 8704;   // free after pass 2 -> stats scratch
  float* ts  = sm + 13056;
  float* scs = sm + 17408;
  float* shs = sm + 17472;
  float* cbs = sm + 17536;
  unsigned char* ls = (unsigned char*)(sm + 17600);
  const int g = blockIdx.x, t = threadIdx.x;
  const int lane = t & 31, wp = t >> 5;
  const int dn = (wp>>1)*16 + (lane>>3);
  const int cw = (wp&1)*32 + (lane&7);

  if(t < 64){
    scs[t]=g_scale[si][t]; shs[t]=g_shift[si][t];
    cbs[t]=__ldg(tb+t)+__ldg(pb+t);
  }
  for(int i=t;i<1024;i+=256){
    int h = i & 63, kq = i >> 6;
    *(float4*)(wA + h*PIT + 4*kq) = __ldg((const float4*)(tw + h*64) + kq);
    *(float4*)(wB + h*PIT + 4*kq) = __ldg((const float4*)(pw + h*64) + kq);
  }
  for(int i=t;i<1024;i+=256) ls[i] = (unsigned char)(__ldg(src + g*1024 + i) & 63);
  for(int i=t;i<1024;i+=256){
    int nn=i>>4, j=i&15;
    *(float4*)(xs + nn*PIT + 4*j) = __ldg((const float4*)(in + (g*64+nn)*64) + j);
  }
  __syncthreads();
  for(int i=t;i<1024;i+=256){
    int nn=i>>4, j=i&15, c=4*j;
    float4 v = *(float4*)(xs + nn*PIT + c);
    v.x=fmaxf(fmaf(v.x,scs[c+0],shs[c+0]),0.f);
    v.y=fmaxf(fmaf(v.y,scs[c+1],shs[c+1]),0.f);
    v.z=fmaxf(fmaf(v.z,scs[c+2],shs[c+2]),0.f);
    v.w=fmaxf(fmaf(v.w,scs[c+3],shs[c+3]),0.f);
    *(float4*)(xs + nn*PIT + c) = v;
  }
  __syncthreads();

  { u64 ta[4][4];
    #pragma unroll
    for(int i=0;i<4;i++)
      #pragma unroll
      for(int r=0;r<4;r++) ta[i][r]=0ull;
    bgemmW(ta, xs, wA, dn, cw);
    #pragma unroll
    for(int i=0;i<4;i++)
      #pragma unroll
      for(int r=0;r<4;r++)
        ts[(dn+4*i)*PIT + cw + 8*r] = f2lo(ta[i][r]) + f2hi(ta[i][r]);
  }
  u64 pa[4][4];
  #pragma unroll
  for(int i=0;i<4;i++)
    #pragma unroll
    for(int r=0;r<4;r++) pa[i][r]=0ull;
  bgemmW(pa, xs, wB, dn, cw);
  __syncthreads();
  #pragma unroll
  for(int i=0;i<4;i++)
    #pragma unroll
    for(int r=0;r<4;r++){
      int c = cw + 8*r, d = dn + 4*i;
      psum[d*PIT + c] = ts[d*PIT + c] + f2lo(pa[i][r]) + f2hi(pa[i][r]) + cbs[c];
    }
  __syncthreads();

  const int n = t>>2, q = t&3, c0 = q*16;
  const unsigned char* lr = ls + n*16;
  float4 mn[4];
  #pragma unroll
  for(int m=0;m<4;m++) mn[m]=make_float4(3e38f,3e38f,3e38f,3e38f);
  #pragma unroll
  for(int j=0;j<16;j++){
    const float4* r = (const float4*)(ts + (int)lr[j]*PIT + c0);
    #pragma unroll
    for(int m=0;m<4;m++) mn[m] = f4min(mn[m], r[m]);
  }
  float* orow = out + (g*64+n)*64;
  #pragma unroll
  for(int m=0;m<4;m++){
    float4 p = *(const float4*)(psum + n*PIT + c0 + 4*m);
    float4 ov = make_float4(p.x-mn[m].x, p.y-mn[m].y, p.z-mn[m].z, p.w-mn[m].w);
    *(float4*)(ys + n*PIT + c0 + 4*m) = ov;
    *(float4*)(orow + c0 + 4*m) = ov;
  }
  __syncthreads();
  stats_store(ys, wB, wB+256, g, t);
}

// ---------- BN finalize: block c reads contiguous partials ----------
__global__ __launch_bounds__(256) void k_final(const float* __restrict__ gam,
                                               const float* __restrict__ bet, int si){
  __shared__ float sa[8], sb[8];
  const int c = blockIdx.x, t = threadIdx.x;
  const int lane = t & 31, wpid = t >> 5;
  float4 a = __ldcg((const float4*)(g_ps + c*NG) + t);
  float4 b = __ldcg((const float4*)(g_pq + c*NG) + t);
  float s1 = a.x+a.y+a.z+a.w;
  float sq = b.x+b.y+b.z+b.w;
  #pragma unroll
  for(int o=16;o>0;o>>=1){
    s1 += __shfl_xor_sync(0xffffffffu, s1, o);
    sq += __shfl_xor_sync(0xffffffffu, sq, o);
  }
  if(lane == 0){ sa[wpid] = s1; sb[wpid] = sq; }
  __syncthreads();
  if(t == 0){
    float S1 = 0.f, SQ = 0.f;
    #pragma unroll
    for(int i=0;i<8;i++){ S1 += sa[i]; SQ += sb[i]; }
    float mu  = S1*(1.f/(float)NN);
    float var = SQ*(1.f/(float)NN) - mu*mu;
    float sc  = __ldg(gam+c) * rsqrtf(var + 1e-5f);
    g_scale[si][c] = sc; g_shift[si][c] = __ldg(bet+c) - mu*sc;
  }
}

// ---------- final BN+ReLU + mean pool (coalesced) ----------
__global__ __launch_bounds__(256) void k_pool(const float* __restrict__ in,
                                              float* __restrict__ out){
  __shared__ float sp[1024];
  const int g = blockIdx.x, t = threadIdx.x;
  const int j = t & 15, row0 = t >> 4, c0 = 4*j;
  float sc0=g_scale[4][c0+0], sc1=g_scale[4][c0+1], sc2=g_scale[4][c0+2], sc3=g_scale[4][c0+3];
  float sh0=g_shift[4][c0+0], sh1=g_shift[4][c0+1], sh2=g_shift[4][c0+2], sh3=g_shift[4][c0+3];
  float4 acc = make_float4(0.f,0.f,0.f,0.f);
  #pragma unroll
  for(int r=0;r<4;r++){
    int nn = row0 + 16*r;
    float4 v = __ldg((const float4*)(in + (g*64+nn)*64 + c0));
    acc.x += fmaxf(fmaf(v.x,sc0,sh0),0.f);
    acc.y += fmaxf(fmaf(v.y,sc1,sh1),0.f);
    acc.z += fmaxf(fmaf(v.z,sc2,sh2),0.f);
    acc.w += fmaxf(fmaf(v.w,sc3,sh3),0.f);
  }
  *(float4*)(sp + row0*64 + c0) = acc;
  __syncthreads();
  if(t < 64){
    float s = 0.f;
    #pragma unroll
    for(int k=0;k<16;k++) s += sp[k*64 + t];
    out[g*64 + t] = s*(1.f/64.f);
  }
}

extern "C" void kernel_launch(void* const* d_in, const int* in_sizes, int n_in,
                              void* d_out, int out_size){
  const float* feat = (const float*)d_in[0];
  const int*   src  = (const int*)d_in[1];
  const float *c1w=(const float*)d_in[4],  *c1b=(const float*)d_in[5];
  const float *bn1g=(const float*)d_in[6], *bn1b=(const float*)d_in[7];
  const float *e1tw=(const float*)d_in[8], *e1tb=(const float*)d_in[9];
  const float *e1pw=(const float*)d_in[10],*e1pb=(const float*)d_in[11];
  const float *bne1g=(const float*)d_in[12],*bne1b=(const float*)d_in[13];
  const float *c2w=(const float*)d_in[14], *c2b=(const float*)d_in[15];
  const float *bn2g=(const float*)d_in[16],*bn2b=(const float*)d_in[17];
  const float *e2tw=(const float*)d_in[18],*e2tb=(const float*)d_in[19];
  const float *e2pw=(const float*)d_in[20],*e2pb=(const float*)d_in[21];
  const float *bne2g=(const float*)d_in[22],*bne2b=(const float*)d_in[23];
  const float *c3w=(const float*)d_in[24], *c3b=(const float*)d_in[25];
  const float *bn3g=(const float*)d_in[26],*bn3b=(const float*)d_in[27];
  float* out = (float*)d_out;

  const int SM1 = 11776*4;
  const int SMH = 17544*4;
  const int SME = 17864*4;
  cudaFuncSetAttribute(k_cheb1, cudaFuncAttributeMaxDynamicSharedMemorySize, SM1);
  cudaFuncSetAttribute(k_chebH, cudaFuncAttributeMaxDynamicSharedMemorySize, SMH);
  cudaFuncSetAttribute(k_econv, cudaFuncAttributeMaxDynamicSharedMemorySize, SME);

  float *bufA, *bufB;
  cudaGetSymbolAddress((void**)&bufA, g_bufA);
  cudaGetSymbolAddress((void**)&bufB, g_bufB);

  k_cheb1<<<NG, 256, SM1>>>(feat, src, c1w, c1b);
  k_final<<<64, 256>>>(bn1g, bn1b, 0);
  k_econv<<<NG, 256, SME>>>(e1tw, e1tb, e1pw, e1pb, 0, src, bufA, bufB);
  k_final<<<64, 256>>>(bne1g, bne1b, 1);
  k_chebH<<<NG, 256, SMH>>>(c2w, c2b, 1, src, bufB, bufA);
  k_final<<<64, 256>>>(bn2g, bn2b, 2);
  k_econv<<<NG, 256, SME>>>(e2tw, e2tb, e2pw, e2pb, 2, src, bufA, bufB);
  k_final<<<64, 256>>>(bne2g, bne2b, 3);
  k_chebH<<<NG, 256, SMH>>>(c3w, c3b, 3, src, bufB, bufA);
  k_final<<<64, 256>>>(bn3g, bn3b, 4);
  k_pool<<<NG, 256>>>(bufA, out);
}

// round 12
// speedup vs baseline: 2.4020x; 1.0769x over previous
#include <cuda_runtime.h>
#include <math.h>

#define NN   65536
#define NG   1024
#define PIT  68

typedef unsigned long long u64;

__device__ __align__(16) float g_bufA[NN*64];
__device__ __align__(16) float g_bufB[NN*64];
__device__ __align__(16) float g_ps[64*NG];   // channel-major partial sums
__device__ __align__(16) float g_pq[64*NG];   // channel-major partial sumsq
__device__ float g_scale[5][64];
__device__ float g_shift[5][64];

static __device__ __forceinline__ u64 f2fma(u64 a, u64 b, u64 c){
  u64 d; asm("fma.rn.f32x2 %0, %1, %2, %3;" : "=l"(d) : "l"(a), "l"(b), "l"(c)); return d;
}
static __device__ __forceinline__ u64 f2add(u64 a, u64 b){
  u64 d; asm("add.rn.f32x2 %0, %1, %2;" : "=l"(d) : "l"(a), "l"(b)); return d;
}
static __device__ __forceinline__ u64 f2mul(u64 a, u64 b){
  u64 d; asm("mul.rn.f32x2 %0, %1, %2;" : "=l"(d) : "l"(a), "l"(b)); return d;
}
static __device__ __forceinline__ u64 f2pack(float x, float y){
  u64 d; asm("mov.b64 %0, {%1,%2};" : "=l"(d) : "f"(x), "f"(y)); return d;
}
static __device__ __forceinline__ float f2lo(u64 a){ return __uint_as_float((unsigned)a); }
static __device__ __forceinline__ float f2hi(u64 a){ return __uint_as_float((unsigned)(a>>32)); }

static __device__ __forceinline__ float4 f4min(float4 a, float4 b){
  return make_float4(fminf(a.x,b.x),fminf(a.y,b.y),fminf(a.z,b.z),fminf(a.w,b.w));
}

// ---- balanced W-GEMM: out[dn+4i][cw+8r] += X[n][k].W[c][k], f32x2 over k ----
static __device__ __forceinline__ void bgemmW(u64 acc[4][4], const float* X, const float* W,
                                              int dn, int cw){
  #pragma unroll 2
  for(int ch=0;ch<16;ch++){
    ulonglong2 xv[4], wv[4];
    #pragma unroll
    for(int i=0;i<4;i++) xv[i] = *(const ulonglong2*)(X + (dn+4*i)*PIT + 4*ch);
    #pragma unroll
    for(int r=0;r<4;r++) wv[r] = *(const ulonglong2*)(W + (cw+8*r)*PIT + 4*ch);
    #pragma unroll
    for(int i=0;i<4;i++)
      #pragma unroll
      for(int r=0;r<4;r++){
        acc[i][r]=f2fma(xv[i].x, wv[r].x, acc[i][r]);
        acc[i][r]=f2fma(xv[i].y, wv[r].y, acc[i][r]);
      }
  }
}

// ---- balanced S-GEMM: out[dn+4i][cs..cs+3] += S[d][s].X[s][c], f32x2 over c ----
static __device__ __forceinline__ void bgemmS(u64 acc[4][2], const float* S, const float* X,
                                              int dn, int cs){
  #pragma unroll 2
  for(int sc=0;sc<16;sc++){
    float av[4][4]; ulonglong2 bv[4];
    #pragma unroll
    for(int i=0;i<4;i++) *(float4*)av[i] = *(const float4*)(S + (dn+4*i)*PIT + 4*sc);
    #pragma unroll
    for(int u=0;u<4;u++) bv[u] = *(const ulonglong2*)(X + (4*sc+u)*PIT + cs);
    #pragma unroll
    for(int i=0;i<4;i++)
      #pragma unroll
      for(int u=0;u<4;u++){
        u64 p = f2pack(av[i][u], av[i][u]);
        acc[i][0]=f2fma(p, bv[u].x, acc[i][0]);
        acc[i][1]=f2fma(p, bv[u].y, acc[i][1]);
      }
  }
}

// ---- per-CTA stats: 256 threads, channel-major global partials ----
static __device__ __forceinline__ void stats_store(const float* ys, float* pp, float* qq,
                                                   int g, int t){
  const int c = t & 63, qu = t >> 6;
  float s = 0.f, s2 = 0.f;
  #pragma unroll
  for(int k=0;k<16;k++){
    float v = ys[(qu*16+k)*PIT + c];
    s += v; s2 += v*v;
  }
  pp[qu*64+c] = s; qq[qu*64+c] = s2;
  __syncthreads();
  if(t < 64){
    g_ps[t*NG+g] = pp[t]+pp[t+64]+pp[t+128]+pp[t+192];
    g_pq[t*NG+g] = qq[t]+qq[t+64]+qq[t+128]+qq[t+192];
  }
}

// =============== cheb layer 1: feat (N,16) -> pre-BN (N,64) ===============
__global__ __launch_bounds__(256,3) void k_cheb1(const float* __restrict__ feat,
                                                 const int* __restrict__ src,
                                                 const float* __restrict__ w,
                                                 const float* __restrict__ b){
  extern __shared__ float sm[];
  float* xs = sm;            // 64*20
  float* x1 = sm + 1280;
  float* x2 = sm + 2560;
  float* wt = sm + 3840;     // pitch 52; free after GEMM -> stats scratch
  float* ys = sm + 7168;     // 64*68
  unsigned char* ls = (unsigned char*)(sm + 11520);
  const int g = blockIdx.x, t = threadIdx.x;

  for(int i=t;i<768;i+=256){
    int h = i & 63, kq = i >> 6;
    *(float4*)(wt + h*52 + 4*kq) = __ldg((const float4*)(w + h*48) + kq);
  }
  for(int i=t;i<256;i+=256){
    int nn = i>>2, j = i&3;
    *(float4*)(xs + nn*20 + 4*j) = __ldg((const float4*)(feat + (g*64+nn)*16) + j);
  }
  for(int i=t;i<1024;i+=256) ls[i] = (unsigned char)(__ldg(src + g*1024 + i) & 63);
  __syncthreads();

  const int n = t>>2, q = t&3, c0 = 4*q;
  const unsigned char* lr = ls + n*16;
  const u64 cm16 = f2pack(-0.0625f,-0.0625f);
  const u64 c125 = f2pack(0.125f,0.125f);
  const u64 cm1  = f2pack(-1.f,-1.f);
  { u64 A0=0,A1=0;
    #pragma unroll
    for(int j=0;j<16;j++){
      ulonglong2 r = *(const ulonglong2*)(xs + (int)lr[j]*20 + c0);
      A0 = f2add(A0, r.x); A1 = f2add(A1, r.y);
    }
    ulonglong2 o; o.x = f2mul(A0, cm16); o.y = f2mul(A1, cm16);
    *(ulonglong2*)(x1 + n*20 + c0) = o; }
  __syncthreads();
  { u64 A0=0,A1=0;
    #pragma unroll
    for(int j=0;j<16;j++){
      ulonglong2 r = *(const ulonglong2*)(x1 + (int)lr[j]*20 + c0);
      A0 = f2add(A0, r.x); A1 = f2add(A1, r.y);
    }
    ulonglong2 X0 = *(const ulonglong2*)(xs + n*20 + c0);
    ulonglong2 o;
    o.x = f2mul(f2fma(A0, c125, X0.x), cm1);
    o.y = f2mul(f2fma(A1, c125, X0.y), cm1);
    *(ulonglong2*)(x2 + n*20 + c0) = o; }
  __syncthreads();

  const int c4 = t & 15, n0 = (t>>4)*4;
  u64 acc[4][4];
  #pragma unroll
  for(int i=0;i<4;i++)
    #pragma unroll
    for(int j=0;j<4;j++) acc[i][j] = 0ull;
  const float* bufs[3] = {xs, x1, x2};
  #pragma unroll
  for(int seg=0;seg<3;seg++){
    const float* X = bufs[seg];
    #pragma unroll
    for(int ch=0;ch<4;ch++){
      ulonglong2 xv[4];
      #pragma unroll
      for(int i=0;i<4;i++) xv[i] = *(const ulonglong2*)(X + (n0+i)*20 + 4*ch);
      #pragma unroll
      for(int j=0;j<4;j++){
        ulonglong2 wv = *(const ulonglong2*)(wt + (c4+16*j)*52 + seg*16 + 4*ch);
        #pragma unroll
        for(int i=0;i<4;i++){
          acc[i][j] = f2fma(xv[i].x, wv.x, acc[i][j]);
          acc[i][j] = f2fma(xv[i].y, wv.y, acc[i][j]);
        }
      }
    }
  }
  __syncthreads();
  float bj[4];
  #pragma unroll
  for(int j=0;j<4;j++) bj[j] = __ldg(b + c4 + 16*j);
  float* obase = g_bufA + (g*64+n0)*64;
  #pragma unroll
  for(int i=0;i<4;i++)
    #pragma unroll
    for(int j=0;j<4;j++){
      float v = f2lo(acc[i][j]) + f2hi(acc[i][j]) + bj[j];
      ys[(n0+i)*PIT + c4 + 16*j] = v;
      obase[i*64 + c4 + 16*j] = v;
    }
  __syncthreads();
  stats_store(ys, wt, wt+256, g, t);
}

// =============== cheb layers 2/3: laps as S-GEMMs ===============
__global__ __launch_bounds__(256,3) void k_chebH(const float* __restrict__ w,
                                                 const float* __restrict__ b,
                                                 int si, const int* __restrict__ src,
                                                 const float* __restrict__ in,
                                                 float* __restrict__ out){
  extern __shared__ float sm[];
  float* xs  = sm;
  float* x1  = sm + 4352;
  float* S   = sm + 8704;
  float* wt  = sm + 13056;
  float* scs = sm + 17408;
  float* shs = sm + 17472;
  float* ys  = x1;
  const int g = blockIdx.x, t = threadIdx.x;
  const int lane = t & 31, wp = t >> 5;
  const int dn = (wp>>1)*16 + (lane>>3);
  const int cs = (wp&1)*32 + (lane&7)*4;
  const int cw = (wp&1)*32 + (lane&7);

  if(t < 64){ scs[t] = g_scale[si][t]; shs[t] = g_shift[si][t]; }
  { float4 z = make_float4(0.f,0.f,0.f,0.f);
    for(int i=t;i<1088;i+=256) ((float4*)S)[i] = z; }
  for(int i=t;i<1024;i+=256){
    int nn=i>>4, j=i&15;
    *(float4*)(xs + nn*PIT + 4*j) = __ldg((const float4*)(in + (g*64+nn)*64) + j);
  }
  for(int i=t;i<1024;i+=256){
    int h=i&63, kq=i>>6;
    *(float4*)(wt + h*PIT + 4*kq) = __ldg((const float4*)(w + h*192) + kq);
  }
  __syncthreads();
  for(int i=t;i<1024;i+=256){
    int nn=i>>4, j=i&15, c=4*j;
    float4 v = *(float4*)(xs + nn*PIT + c);
    v.x=fmaxf(fmaf(v.x,scs[c+0],shs[c+0]),0.f);
    v.y=fmaxf(fmaf(v.y,scs[c+1],shs[c+1]),0.f);
    v.z=fmaxf(fmaf(v.z,scs[c+2],shs[c+2]),0.f);
    v.w=fmaxf(fmaf(v.w,scs[c+3],shs[c+3]),0.f);
    *(float4*)(xs + nn*PIT + c) = v;
  }
  for(int i=t;i<1024;i+=256){
    int sl = __ldg(src + g*1024 + i) & 63;
    atomicAdd(S + (i>>4)*PIT + sl, -0.0625f);
  }
  __syncthreads();

  u64 aW[4][4];
  #pragma unroll
  for(int i=0;i<4;i++)
    #pragma unroll
    for(int r=0;r<4;r++) aW[i][r] = 0ull;

  bgemmW(aW, xs, wt, dn, cw);
  { u64 aS[4][2] = {{0,0},{0,0},{0,0},{0,0}};
    bgemmS(aS, S, xs, dn, cs);
    #pragma unroll
    for(int i=0;i<4;i++){
      ulonglong2 o; o.x = aS[i][0]; o.y = aS[i][1];
      *(ulonglong2*)(x1 + (dn+4*i)*PIT + cs) = o;
    }
  }
  __syncthreads();
  for(int i=t;i<1024;i+=256){
    int h=i&63, kq=i>>6;
    *(float4*)(wt + h*PIT + 4*kq) = __ldg((const float4*)(w + h*192) + 16 + kq);
  }
  __syncthreads();
  bgemmW(aW, x1, wt, dn, cw);
  { u64 aS[4][2] = {{0,0},{0,0},{0,0},{0,0}};
    bgemmS(aS, S, x1, dn, cs);
    const u64 two = f2pack(2.f,2.f), mone = f2pack(-1.f,-1.f);
    #pragma unroll
    for(int i=0;i<4;i++){
      ulonglong2 x0 = *(const ulonglong2*)(xs + (dn+4*i)*PIT + cs);
      ulonglong2 o;
      o.x = f2fma(two, aS[i][0], f2mul(x0.x, mone));
      o.y = f2fma(two, aS[i][1], f2mul(x0.y, mone));
      *(ulonglong2*)(xs + (dn+4*i)*PIT + cs) = o;
    }
  }
  __syncthreads();
  for(int i=t;i<1024;i+=256){
    int h=i&63, kq=i>>6;
    *(float4*)(wt + h*PIT + 4*kq) = __ldg((const float4*)(w + h*192) + 32 + kq);
  }
  __syncthreads();
  bgemmW(aW, xs, wt, dn, cw);
  __syncthreads();           // wt free; x1 (=ys) writable
  { float bj[4];
    #pragma unroll
    for(int r=0;r<4;r++) bj[r] = __ldg(b + cw + 8*r);
    #pragma unroll
    for(int i=0;i<4;i++)
      #pragma unroll
      for(int r=0;r<4;r++)
        ys[(dn+4*i)*PIT + cw + 8*r] = f2lo(aW[i][r]) + f2hi(aW[i][r]) + bj[r];
  }
  __syncthreads();
  for(int i=t;i<1024;i+=256){
    int nn=i>>4, j=i&15;
    *(float4*)(out + (g*64+nn)*64 + 4*j) = *(const float4*)(ys + nn*PIT + 4*j);
  }
  stats_store(ys, wt, wt+256, g, t);
}

// =============== edge conv: balanced GEMMs, conflict-free min ===============
__global__ __launch_bounds__(256,3) void k_econv(const float* __restrict__ tw,
                                                 const float* __restrict__ tb,
                                                 const float* __restrict__ pw,
                                                 const float* __restrict__ pb,
                                                 int si, const int* __restrict__ src,
                                                 const float* __restrict__ in,
                                                 float* __restrict__ out){
  extern __shared__ float sm[];
  float* xs  = sm;          float* psum = sm;
  float* wA  = sm + 4352;   float* ys   = sm + 4352;
  float* wB  = sm + 8704;   // free after pass 2 -> stats scratch
  float* ts  = sm + 13056;
  float* scs = sm + 17408;
  float* shs = sm + 17472;
  float* cbs = sm + 17536;
  unsigned char* ls = (unsigned char*)(sm + 17600);
  const int g = blockIdx.x, t = threadIdx.x;
  const int lane = t & 31, wp = t >> 5;
  const int dn = (wp>>1)*16 + (lane>>3);
  const int cw = (wp&1)*32 + (lane&7);

  if(t < 64){
    scs[t]=g_scale[si][t]; shs[t]=g_shift[si][t];
    cbs[t]=__ldg(tb+t)+__ldg(pb+t);
  }
  for(int i=t;i<1024;i+=256){
    int h = i & 63, kq = i >> 6;
    *(float4*)(wA + h*PIT + 4*kq) = __ldg((const float4*)(tw + h*64) + kq);
    *(float4*)(wB + h*PIT + 4*kq) = __ldg((const float4*)(pw + h*64) + kq);
  }
  for(int i=t;i<1024;i+=256) ls[i] = (unsigned char)(__ldg(src + g*1024 + i) & 63);
  for(int i=t;i<1024;i+=256){
    int nn=i>>4, j=i&15;
    *(float4*)(xs + nn*PIT + 4*j) = __ldg((const float4*)(in + (g*64+nn)*64) + j);
  }
  __syncthreads();
  for(int i=t;i<1024;i+=256){
    int nn=i>>4, j=i&15, c=4*j;
    float4 v = *(float4*)(xs + nn*PIT + c);
    v.x=fmaxf(fmaf(v.x,scs[c+0],shs[c+0]),0.f);
    v.y=fmaxf(fmaf(v.y,scs[c+1],shs[c+1]),0.f);
    v.z=fmaxf(fmaf(v.z,scs[c+2],shs[c+2]),0.f);
    v.w=fmaxf(fmaf(v.w,scs[c+3],shs[c+3]),0.f);
    *(float4*)(xs + nn*PIT + c) = v;
  }
  __syncthreads();

  { u64 ta[4][4];
    #pragma unroll
    for(int i=0;i<4;i++)
      #pragma unroll
      for(int r=0;r<4;r++) ta[i][r]=0ull;
    bgemmW(ta, xs, wA, dn, cw);
    #pragma unroll
    for(int i=0;i<4;i++)
      #pragma unroll
      for(int r=0;r<4;r++)
        ts[(dn+4*i)*PIT + cw + 8*r] = f2lo(ta[i][r]) + f2hi(ta[i][r]);
  }
  u64 pa[4][4];
  #pragma unroll
  for(int i=0;i<4;i++)
    #pragma unroll
    for(int r=0;r<4;r++) pa[i][r]=0ull;
  bgemmW(pa, xs, wB, dn, cw);
  __syncthreads();
  #pragma unroll
  for(int i=0;i<4;i++)
    #pragma unroll
    for(int r=0;r<4;r++){
      int c = cw + 8*r, d = dn + 4*i;
      psum[d*PIT + c] = ts[d*PIT + c] + f2lo(pa[i][r]) + f2hi(pa[i][r]) + cbs[c];
    }
  __syncthreads();

  // min over neighbors: paired full-row reads, conflict-free by construction.
  // lanes 0-15 read row lr[2j], lanes 16-31 read row lr[2j+1]; each lane a
  // contiguous 16B channel slice; halves merged via shfl_xor(16).
  const int half = lane >> 4;
  const int cl = (lane & 15) * 4;
  const int wd0 = wp * 8;
  #pragma unroll 2
  for(int d = wd0; d < wd0 + 8; d++){
    uint4 lm = *(const uint4*)(ls + d*16);
    float4 mn = make_float4(3e38f,3e38f,3e38f,3e38f);
    #pragma unroll
    for(int jj=0;jj<8;jj++){
      unsigned word = (jj>>1)==0 ? lm.x : (jj>>1)==1 ? lm.y : (jj>>1)==2 ? lm.z : lm.w;
      int sh = (((2*jj) & 3) + half) * 8;
      int row = (int)((word >> sh) & 63u);
      mn = f4min(mn, *(const float4*)(ts + row*PIT + cl));
    }
    mn.x = fminf(mn.x, __shfl_xor_sync(0xffffffffu, mn.x, 16));
    mn.y = fminf(mn.y, __shfl_xor_sync(0xffffffffu, mn.y, 16));
    mn.z = fminf(mn.z, __shfl_xor_sync(0xffffffffu, mn.z, 16));
    mn.w = fminf(mn.w, __shfl_xor_sync(0xffffffffu, mn.w, 16));
    if(half == 0){
      float4 p = *(const float4*)(psum + d*PIT + cl);
      float4 ov = make_float4(p.x-mn.x, p.y-mn.y, p.z-mn.z, p.w-mn.w);
      *(float4*)(ys + d*PIT + cl) = ov;
      *(float4*)(out + (g*64+d)*64 + cl) = ov;
    }
  }
  __syncthreads();
  stats_store(ys, wB, wB+256, g, t);
}

// ---------- BN finalize: block c reads contiguous partials ----------
__global__ __launch_bounds__(256) void k_final(const float* __restrict__ gam,
                                               const float* __restrict__ bet, int si){
  __shared__ float sa[8], sb[8];
  const int c = blockIdx.x, t = threadIdx.x;
  const int lane = t & 31, wpid = t >> 5;
  float4 a = __ldcg((const float4*)(g_ps + c*NG) + t);
  float4 b = __ldcg((const float4*)(g_pq + c*NG) + t);
  float s1 = a.x+a.y+a.z+a.w;
  float sq = b.x+b.y+b.z+b.w;
  #pragma unroll
  for(int o=16;o>0;o>>=1){
    s1 += __shfl_xor_sync(0xffffffffu, s1, o);
    sq += __shfl_xor_sync(0xffffffffu, sq, o);
  }
  if(lane == 0){ sa[wpid] = s1; sb[wpid] = sq; }
  __syncthreads();
  if(t == 0){
    float S1 = 0.f, SQ = 0.f;
    #pragma unroll
    for(int i=0;i<8;i++){ S1 += sa[i]; SQ += sb[i]; }
    float mu  = S1*(1.f/(float)NN);
    float var = SQ*(1.f/(float)NN) - mu*mu;
    float sc  = __ldg(gam+c) * rsqrtf(var + 1e-5f);
    g_scale[si][c] = sc; g_shift[si][c] = __ldg(bet+c) - mu*sc;
  }
}

// ---------- final BN+ReLU + mean pool (coalesced) ----------
__global__ __launch_bounds__(256) void k_pool(const float* __restrict__ in,
                                              float* __restrict__ out){
  __shared__ float sp[1024];
  const int g = blockIdx.x, t = threadIdx.x;
  const int j = t & 15, row0 = t >> 4, c0 = 4*j;
  float sc0=g_scale[4][c0+0], sc1=g_scale[4][c0+1], sc2=g_scale[4][c0+2], sc3=g_scale[4][c0+3];
  float sh0=g_shift[4][c0+0], sh1=g_shift[4][c0+1], sh2=g_shift[4][c0+2], sh3=g_shift[4][c0+3];
  float4 acc = make_float4(0.f,0.f,0.f,0.f);
  #pragma unroll
  for(int r=0;r<4;r++){
    int nn = row0 + 16*r;
    float4 v = __ldg((const float4*)(in + (g*64+nn)*64 + c0));
    acc.x += fmaxf(fmaf(v.x,sc0,sh0),0.f);
    acc.y += fmaxf(fmaf(v.y,sc1,sh1),0.f);
    acc.z += fmaxf(fmaf(v.z,sc2,sh2),0.f);
    acc.w += fmaxf(fmaf(v.w,sc3,sh3),0.f);
  }
  *(float4*)(sp + row0*64 + c0) = acc;
  __syncthreads();
  if(t < 64){
    float s = 0.f;
    #pragma unroll
    for(int k=0;k<16;k++) s += sp[k*64 + t];
    out[g*64 + t] = s*(1.f/64.f);
  }
}

extern "C" void kernel_launch(void* const* d_in, const int* in_sizes, int n_in,
                              void* d_out, int out_size){
  const float* feat = (const float*)d_in[0];
  const int*   src  = (const int*)d_in[1];
  const float *c1w=(const float*)d_in[4],  *c1b=(const float*)d_in[5];
  const float *bn1g=(const float*)d_in[6], *bn1b=(const float*)d_in[7];
  const float *e1tw=(const float*)d_in[8], *e1tb=(const float*)d_in[9];
  const float *e1pw=(const float*)d_in[10],*e1pb=(const float*)d_in[11];
  const float *bne1g=(const float*)d_in[12],*bne1b=(const float*)d_in[13];
  const float *c2w=(const float*)d_in[14], *c2b=(const float*)d_in[15];
  const float *bn2g=(const float*)d_in[16],*bn2b=(const float*)d_in[17];
  const float *e2tw=(const float*)d_in[18],*e2tb=(const float*)d_in[19];
  const float *e2pw=(const float*)d_in[20],*e2pb=(const float*)d_in[21];
  const float *bne2g=(const float*)d_in[22],*bne2b=(const float*)d_in[23];
  const float *c3w=(const float*)d_in[24], *c3b=(const float*)d_in[25];
  const float *bn3g=(const float*)d_in[26],*bn3b=(const float*)d_in[27];
  float* out = (float*)d_out;

  const int SM1 = 11776*4;
  const int SMH = 17544*4;
  const int SME = 17864*4;
  cudaFuncSetAttribute(k_cheb1, cudaFuncAttributeMaxDynamicSharedMemorySize, SM1);
  cudaFuncSetAttribute(k_chebH, cudaFuncAttributeMaxDynamicSharedMemorySize, SMH);
  cudaFuncSetAttribute(k_econv, cudaFuncAttributeMaxDynamicSharedMemorySize, SME);

  float *bufA, *bufB;
  cudaGetSymbolAddress((void**)&bufA, g_bufA);
  cudaGetSymbolAddress((void**)&bufB, g_bufB);

  k_cheb1<<<NG, 256, SM1>>>(feat, src, c1w, c1b);
  k_final<<<64, 256>>>(bn1g, bn1b, 0);
  k_econv<<<NG, 256, SME>>>(e1tw, e1tb, e1pw, e1pb, 0, src, bufA, bufB);
  k_final<<<64, 256>>>(bne1g, bne1b, 1);
  k_chebH<<<NG, 256, SMH>>>(c2w, c2b, 1, src, bufB, bufA);
  k_final<<<64, 256>>>(bn2g, bn2b, 2);
  k_econv<<<NG, 256, SME>>>(e2tw, e2tb, e2pw, e2pb, 2, src, bufA, bufB);
  k_final<<<64, 256>>>(bne2g, bne2b, 3);
  k_chebH<<<NG, 256, SMH>>>(c3w, c3b, 3, src, bufB, bufA);
  k_final<<<64, 256>>>(bn3g, bn3b, 4);
  k_pool<<<NG, 256>>>(bufA, out);
}

// round 13
// speedup vs baseline: 2.4710x; 1.0287x over previous
#include <cuda_runtime.h>
#include <math.h>

#define NN   65536
#define NG   1024
#define PIT  68

typedef unsigned long long u64;

__device__ __align__(16) float g_bufA[NN*64];
__device__ __align__(16) float g_bufB[NN*64];
__device__ __align__(16) float g_sum[5][64];
__device__ __align__(16) float g_sq [5][64];

static __device__ __forceinline__ u64 f2fma(u64 a, u64 b, u64 c){
  u64 d; asm("fma.rn.f32x2 %0, %1, %2, %3;" : "=l"(d) : "l"(a), "l"(b), "l"(c)); return d;
}
static __device__ __forceinline__ u64 f2add(u64 a, u64 b){
  u64 d; asm("add.rn.f32x2 %0, %1, %2;" : "=l"(d) : "l"(a), "l"(b)); return d;
}
static __device__ __forceinline__ u64 f2mul(u64 a, u64 b){
  u64 d; asm("mul.rn.f32x2 %0, %1, %2;" : "=l"(d) : "l"(a), "l"(b)); return d;
}
static __device__ __forceinline__ u64 f2pack(float x, float y){
  u64 d; asm("mov.b64 %0, {%1,%2};" : "=l"(d) : "f"(x), "f"(y)); return d;
}
static __device__ __forceinline__ float f2lo(u64 a){ return __uint_as_float((unsigned)a); }
static __device__ __forceinline__ float f2hi(u64 a){ return __uint_as_float((unsigned)(a>>32)); }

static __device__ __forceinline__ float4 f4min(float4 a, float4 b){
  return make_float4(fminf(a.x,b.x),fminf(a.y,b.y),fminf(a.z,b.z),fminf(a.w,b.w));
}

// ---- balanced W-GEMM: out[dn+4i][cw+8r] += X[n][k].W[c][k], f32x2 over k ----
static __device__ __forceinline__ void bgemmW(u64 acc[4][4], const float* X, const float* W,
                                              int dn, int cw){
  #pragma unroll 2
  for(int ch=0;ch<16;ch++){
    ulonglong2 xv[4], wv[4];
    #pragma unroll
    for(int i=0;i<4;i++) xv[i] = *(const ulonglong2*)(X + (dn+4*i)*PIT + 4*ch);
    #pragma unroll
    for(int r=0;r<4;r++) wv[r] = *(const ulonglong2*)(W + (cw+8*r)*PIT + 4*ch);
    #pragma unroll
    for(int i=0;i<4;i++)
      #pragma unroll
      for(int r=0;r<4;r++){
        acc[i][r]=f2fma(xv[i].x, wv[r].x, acc[i][r]);
        acc[i][r]=f2fma(xv[i].y, wv[r].y, acc[i][r]);
      }
  }
}

// ---- balanced S-GEMM: out[dn+4i][cs..cs+3] += S[d][s].X[s][c], f32x2 over c ----
static __device__ __forceinline__ void bgemmS(u64 acc[4][2], const float* S, const float* X,
                                              int dn, int cs){
  #pragma unroll 2
  for(int sc=0;sc<16;sc++){
    float av[4][4]; ulonglong2 bv[4];
    #pragma unroll
    for(int i=0;i<4;i++) *(float4*)av[i] = *(const float4*)(S + (dn+4*i)*PIT + 4*sc);
    #pragma unroll
    for(int u=0;u<4;u++) bv[u] = *(const ulonglong2*)(X + (4*sc+u)*PIT + cs);
    #pragma unroll
    for(int i=0;i<4;i++)
      #pragma unroll
      for(int u=0;u<4;u++){
        u64 p = f2pack(av[i][u], av[i][u]);
        acc[i][0]=f2fma(p, bv[u].x, acc[i][0]);
        acc[i][1]=f2fma(p, bv[u].y, acc[i][1]);
      }
  }
}

// ---- per-CTA stats -> global channel accumulators (REDG, no fence) ----
static __device__ __forceinline__ void stats_atomic(const float* ys, float* pp, float* qq,
                                                    int t, int si){
  const int c = t & 63, qu = t >> 6;
  float s = 0.f, s2 = 0.f;
  #pragma unroll
  for(int k=0;k<16;k++){
    float v = ys[(qu*16+k)*PIT + c];
    s += v; s2 += v*v;
  }
  pp[qu*64+c] = s; qq[qu*64+c] = s2;
  __syncthreads();
  if(t < 64){
    atomicAdd(&g_sum[si][t], pp[t]+pp[t+64]+pp[t+128]+pp[t+192]);
    atomicAdd(&g_sq [si][t], qq[t]+qq[t+64]+qq[t+128]+qq[t+192]);
  }
}

// ---- reader head: compute scale/shift from accumulated stats ----
static __device__ __forceinline__ void bn_head(float* scs, float* shs, int t, int si,
                                               const float* __restrict__ gam,
                                               const float* __restrict__ bet){
  if(t < 64){
    float s1 = __ldcg(&g_sum[si][t]);
    float sq = __ldcg(&g_sq [si][t]);
    float mu  = s1*(1.f/(float)NN);
    float var = sq*(1.f/(float)NN) - mu*mu;
    float sc  = __ldg(gam+t) * rsqrtf(var + 1e-5f);
    scs[t] = sc; shs[t] = __ldg(bet+t) - mu*sc;
  }
}

__global__ void k_zero(){
  int i = threadIdx.x;
  if(i < 320){ ((float*)g_sum)[i] = 0.f; ((float*)g_sq)[i] = 0.f; }
}

// =============== cheb layer 1: feat (N,16) -> pre-BN (N,64) ===============
__global__ __launch_bounds__(256,3) void k_cheb1(const float* __restrict__ feat,
                                                 const int* __restrict__ src,
                                                 const float* __restrict__ w,
                                                 const float* __restrict__ b){
  extern __shared__ float sm[];
  float* xs = sm;            // 64*20
  float* x1 = sm + 1280;
  float* x2 = sm + 2560;
  float* wt = sm + 3840;     // pitch 52; free after GEMM -> stats scratch
  float* ys = sm + 7168;     // 64*68
  unsigned char* ls = (unsigned char*)(sm + 11520);
  const int g = blockIdx.x, t = threadIdx.x;

  for(int i=t;i<768;i+=256){
    int h = i & 63, kq = i >> 6;
    *(float4*)(wt + h*52 + 4*kq) = __ldg((const float4*)(w + h*48) + kq);
  }
  for(int i=t;i<256;i+=256){
    int nn = i>>2, j = i&3;
    *(float4*)(xs + nn*20 + 4*j) = __ldg((const float4*)(feat + (g*64+nn)*16) + j);
  }
  for(int i=t;i<1024;i+=256) ls[i] = (unsigned char)(__ldg(src + g*1024 + i) & 63);
  __syncthreads();

  const int n = t>>2, q = t&3, c0 = 4*q;
  const unsigned char* lr = ls + n*16;
  const u64 cm16 = f2pack(-0.0625f,-0.0625f);
  const u64 c125 = f2pack(0.125f,0.125f);
  const u64 cm1  = f2pack(-1.f,-1.f);
  { u64 A0=0,A1=0;
    #pragma unroll
    for(int j=0;j<16;j++){
      ulonglong2 r = *(const ulonglong2*)(xs + (int)lr[j]*20 + c0);
      A0 = f2add(A0, r.x); A1 = f2add(A1, r.y);
    }
    ulonglong2 o; o.x = f2mul(A0, cm16); o.y = f2mul(A1, cm16);
    *(ulonglong2*)(x1 + n*20 + c0) = o; }
  __syncthreads();
  { u64 A0=0,A1=0;
    #pragma unroll
    for(int j=0;j<16;j++){
      ulonglong2 r = *(const ulonglong2*)(x1 + (int)lr[j]*20 + c0);
      A0 = f2add(A0, r.x); A1 = f2add(A1, r.y);
    }
    ulonglong2 X0 = *(const ulonglong2*)(xs + n*20 + c0);
    ulonglong2 o;
    o.x = f2mul(f2fma(A0, c125, X0.x), cm1);
    o.y = f2mul(f2fma(A1, c125, X0.y), cm1);
    *(ulonglong2*)(x2 + n*20 + c0) = o; }
  __syncthreads();

  const int c4 = t & 15, n0 = (t>>4)*4;
  u64 acc[4][4];
  #pragma unroll
  for(int i=0;i<4;i++)
    #pragma unroll
    for(int j=0;j<4;j++) acc[i][j] = 0ull;
  const float* bufs[3] = {xs, x1, x2};
  #pragma unroll
  for(int seg=0;seg<3;seg++){
    const float* X = bufs[seg];
    #pragma unroll
    for(int ch=0;ch<4;ch++){
      ulonglong2 xv[4];
      #pragma unroll
      for(int i=0;i<4;i++) xv[i] = *(const ulonglong2*)(X + (n0+i)*20 + 4*ch);
      #pragma unroll
      for(int j=0;j<4;j++){
        ulonglong2 wv = *(const ulonglong2*)(wt + (c4+16*j)*52 + seg*16 + 4*ch);
        #pragma unroll
        for(int i=0;i<4;i++){
          acc[i][j] = f2fma(xv[i].x, wv.x, acc[i][j]);
          acc[i][j] = f2fma(xv[i].y, wv.y, acc[i][j]);
        }
      }
    }
  }
  __syncthreads();
  float bj[4];
  #pragma unroll
  for(int j=0;j<4;j++) bj[j] = __ldg(b + c4 + 16*j);
  float* obase = g_bufA + (g*64+n0)*64;
  #pragma unroll
  for(int i=0;i<4;i++)
    #pragma unroll
    for(int j=0;j<4;j++){
      float v = f2lo(acc[i][j]) + f2hi(acc[i][j]) + bj[j];
      ys[(n0+i)*PIT + c4 + 16*j] = v;
      obase[i*64 + c4 + 16*j] = v;
    }
  __syncthreads();
  stats_atomic(ys, wt, wt+256, t, 0);
}

// =============== cheb layers 2/3: laps as S-GEMMs ===============
__global__ __launch_bounds__(256,3) void k_chebH(const float* __restrict__ w,
                                                 const float* __restrict__ b,
                                                 int si, int so,
                                                 const float* __restrict__ gam,
                                                 const float* __restrict__ bet,
                                                 const int* __restrict__ src,
                                                 const float* __restrict__ in,
                                                 float* __restrict__ out){
  extern __shared__ float sm[];
  float* xs  = sm;
  float* x1  = sm + 4352;
  float* S   = sm + 8704;
  float* wt  = sm + 13056;
  float* scs = sm + 17408;
  float* shs = sm + 17472;
  float* ys  = x1;
  const int g = blockIdx.x, t = threadIdx.x;
  const int lane = t & 31, wp = t >> 5;
  const int dn = (wp>>1)*16 + (lane>>3);
  const int cs = (wp&1)*32 + (lane&7)*4;
  const int cw = (wp&1)*32 + (lane&7);

  bn_head(scs, shs, t, si, gam, bet);
  { float4 z = make_float4(0.f,0.f,0.f,0.f);
    for(int i=t;i<1088;i+=256) ((float4*)S)[i] = z; }
  for(int i=t;i<1024;i+=256){
    int nn=i>>4, j=i&15;
    *(float4*)(xs + nn*PIT + 4*j) = __ldg((const float4*)(in + (g*64+nn)*64) + j);
  }
  for(int i=t;i<1024;i+=256){
    int h=i&63, kq=i>>6;
    *(float4*)(wt + h*PIT + 4*kq) = __ldg((const float4*)(w + h*192) + kq);
  }
  __syncthreads();
  for(int i=t;i<1024;i+=256){
    int nn=i>>4, j=i&15, c=4*j;
    float4 v = *(float4*)(xs + nn*PIT + c);
    v.x=fmaxf(fmaf(v.x,scs[c+0],shs[c+0]),0.f);
    v.y=fmaxf(fmaf(v.y,scs[c+1],shs[c+1]),0.f);
    v.z=fmaxf(fmaf(v.z,scs[c+2],shs[c+2]),0.f);
    v.w=fmaxf(fmaf(v.w,scs[c+3],shs[c+3]),0.f);
    *(float4*)(xs + nn*PIT + c) = v;
  }
  for(int i=t;i<1024;i+=256){
    int sl = __ldg(src + g*1024 + i) & 63;
    atomicAdd(S + (i>>4)*PIT + sl, -0.0625f);
  }
  __syncthreads();

  u64 aW[4][4];
  #pragma unroll
  for(int i=0;i<4;i++)
    #pragma unroll
    for(int r=0;r<4;r++) aW[i][r] = 0ull;

  bgemmW(aW, xs, wt, dn, cw);
  { u64 aS[4][2] = {{0,0},{0,0},{0,0},{0,0}};
    bgemmS(aS, S, xs, dn, cs);
    #pragma unroll
    for(int i=0;i<4;i++){
      ulonglong2 o; o.x = aS[i][0]; o.y = aS[i][1];
      *(ulonglong2*)(x1 + (dn+4*i)*PIT + cs) = o;
    }
  }
  __syncthreads();
  for(int i=t;i<1024;i+=256){
    int h=i&63, kq=i>>6;
    *(float4*)(wt + h*PIT + 4*kq) = __ldg((const float4*)(w + h*192) + 16 + kq);
  }
  __syncthreads();
  bgemmW(aW, x1, wt, dn, cw);
  { u64 aS[4][2] = {{0,0},{0,0},{0,0},{0,0}};
    bgemmS(aS, S, x1, dn, cs);
    const u64 two = f2pack(2.f,2.f), mone = f2pack(-1.f,-1.f);
    #pragma unroll
    for(int i=0;i<4;i++){
      ulonglong2 x0 = *(const ulonglong2*)(xs + (dn+4*i)*PIT + cs);
      ulonglong2 o;
      o.x = f2fma(two, aS[i][0], f2mul(x0.x, mone));
      o.y = f2fma(two, aS[i][1], f2mul(x0.y, mone));
      *(ulonglong2*)(xs + (dn+4*i)*PIT + cs) = o;
    }
  }
  __syncthreads();
  for(int i=t;i<1024;i+=256){
    int h=i&63, kq=i>>6;
    *(float4*)(wt + h*PIT + 4*kq) = __ldg((const float4*)(w + h*192) + 32 + kq);
  }
  __syncthreads();
  bgemmW(aW, xs, wt, dn, cw);
  __syncthreads();           // wt free; x1 (=ys) writable
  { float bj[4];
    #pragma unroll
    for(int r=0;r<4;r++) bj[r] = __ldg(b + cw + 8*r);
    #pragma unroll
    for(int i=0;i<4;i++)
      #pragma unroll
      for(int r=0;r<4;r++)
        ys[(dn+4*i)*PIT + cw + 8*r] = f2lo(aW[i][r]) + f2hi(aW[i][r]) + bj[r];
  }
  __syncthreads();
  for(int i=t;i<1024;i+=256){
    int nn=i>>4, j=i&15;
    *(float4*)(out + (g*64+nn)*64 + 4*j) = *(const float4*)(ys + nn*PIT + 4*j);
  }
  stats_atomic(ys, wt, wt+256, t, so);
}

// =============== edge conv: balanced GEMMs, conflict-free min ===============
__global__ __launch_bounds__(256,3) void k_econv(const float* __restrict__ tw,
                                                 const float* __restrict__ tb,
                                                 const float* __restrict__ pw,
                                                 const float* __restrict__ pb,
                                                 int si, int so,
                                                 const float* __restrict__ gam,
                                                 const float* __restrict__ bet,
                                                 const int* __restrict__ src,
                                                 const float* __restrict__ in,
                                                 float* __restrict__ out){
  extern __shared__ float sm[];
  float* xs  = sm;          float* psum = sm;
  float* wA  = sm + 4352;   float* ys   = sm + 4352;
  float* wB  = sm + 8704;   // free after pass 2 -> stats scratch
  float* ts  = sm + 13056;
  float* scs = sm + 17408;
  float* shs = sm + 17472;
  float* cbs = sm + 17536;
  unsigned char* ls = (unsigned char*)(sm + 17600);
  const int g = blockIdx.x, t = threadIdx.x;
  const int lane = t & 31, wp = t >> 5;
  const int dn = (wp>>1)*16 + (lane>>3);
  const int cw = (wp&1)*32 + (lane&7);

  bn_head(scs, shs, t, si, gam, bet);
  if(t < 64) cbs[t] = __ldg(tb+t)+__ldg(pb+t);
  for(int i=t;i<1024;i+=256){
    int h = i & 63, kq = i >> 6;
    *(float4*)(wA + h*PIT + 4*kq) = __ldg((const float4*)(tw + h*64) + kq);
    *(float4*)(wB + h*PIT + 4*kq) = __ldg((const float4*)(pw + h*64) + kq);
  }
  for(int i=t;i<1024;i+=256) ls[i] = (unsigned char)(__ldg(src + g*1024 + i) & 63);
  for(int i=t;i<1024;i+=256){
    int nn=i>>4, j=i&15;
    *(float4*)(xs + nn*PIT + 4*j) = __ldg((const float4*)(in + (g*64+nn)*64) + j);
  }
  __syncthreads();
  for(int i=t;i<1024;i+=256){
    int nn=i>>4, j=i&15, c=4*j;
    float4 v = *(float4*)(xs + nn*PIT + c);
    v.x=fmaxf(fmaf(v.x,scs[c+0],shs[c+0]),0.f);
    v.y=fmaxf(fmaf(v.y,scs[c+1],shs[c+1]),0.f);
    v.z=fmaxf(fmaf(v.z,scs[c+2],shs[c+2]),0.f);
    v.w=fmaxf(fmaf(v.w,scs[c+3],shs[c+3]),0.f);
    *(float4*)(xs + nn*PIT + c) = v;
  }
  __syncthreads();

  { u64 ta[4][4];
    #pragma unroll
    for(int i=0;i<4;i++)
      #pragma unroll
      for(int r=0;r<4;r++) ta[i][r]=0ull;
    bgemmW(ta, xs, wA, dn, cw);
    #pragma unroll
    for(int i=0;i<4;i++)
      #pragma unroll
      for(int r=0;r<4;r++)
        ts[(dn+4*i)*PIT + cw + 8*r] = f2lo(ta[i][r]) + f2hi(ta[i][r]);
  }
  u64 pa[4][4];
  #pragma unroll
  for(int i=0;i<4;i++)
    #pragma unroll
    for(int r=0;r<4;r++) pa[i][r]=0ull;
  bgemmW(pa, xs, wB, dn, cw);
  __syncthreads();
  #pragma unroll
  for(int i=0;i<4;i++)
    #pragma unroll
    for(int r=0;r<4;r++){
      int c = cw + 8*r, d = dn + 4*i;
      psum[d*PIT + c] = ts[d*PIT + c] + f2lo(pa[i][r]) + f2hi(pa[i][r]) + cbs[c];
    }
  __syncthreads();

  // min over neighbors: paired full-row reads, conflict-free by construction.
  const int half = lane >> 4;
  const int cl = (lane & 15) * 4;
  const int wd0 = wp * 8;
  #pragma unroll 2
  for(int d = wd0; d < wd0 + 8; d++){
    uint4 lm = *(const uint4*)(ls + d*16);
    float4 mn = make_float4(3e38f,3e38f,3e38f,3e38f);
    #pragma unroll
    for(int jj=0;jj<8;jj++){
      unsigned word = (jj>>1)==0 ? lm.x : (jj>>1)==1 ? lm.y : (jj>>1)==2 ? lm.z : lm.w;
      int sh = (((2*jj) & 3) + half) * 8;
      int row = (int)((word >> sh) & 63u);
      mn = f4min(mn, *(const float4*)(ts + row*PIT + cl));
    }
    mn.x = fminf(mn.x, __shfl_xor_sync(0xffffffffu, mn.x, 16));
    mn.y = fminf(mn.y, __shfl_xor_sync(0xffffffffu, mn.y, 16));
    mn.z = fminf(mn.z, __shfl_xor_sync(0xffffffffu, mn.z, 16));
    mn.w = fminf(mn.w, __shfl_xor_sync(0xffffffffu, mn.w, 16));
    if(half == 0){
      float4 p = *(const float4*)(psum + d*PIT + cl);
      float4 ov = make_float4(p.x-mn.x, p.y-mn.y, p.z-mn.z, p.w-mn.w);
      *(float4*)(ys + d*PIT + cl) = ov;
      *(float4*)(out + (g*64+d)*64 + cl) = ov;
    }
  }
  __syncthreads();
  stats_atomic(ys, wB, wB+256, t, so);
}

// ---------- final BN+ReLU + mean pool (coalesced, inline stats) ----------
__global__ __launch_bounds__(256) void k_pool(const float* __restrict__ gam,
                                              const float* __restrict__ bet,
                                              const float* __restrict__ in,
                                              float* __restrict__ out){
  __shared__ float sp[1024];
  __shared__ float scs[64], shs[64];
  const int g = blockIdx.x, t = threadIdx.x;
  bn_head(scs, shs, t, 4, gam, bet);
  __syncthreads();
  const int j = t & 15, row0 = t >> 4, c0 = 4*j;
  float sc0=scs[c0+0], sc1=scs[c0+1], sc2=scs[c0+2], sc3=scs[c0+3];
  float sh0=shs[c0+0], sh1=shs[c0+1], sh2=shs[c0+2], sh3=shs[c0+3];
  float4 acc = make_float4(0.f,0.f,0.f,0.f);
  #pragma unroll
  for(int r=0;r<4;r++){
    int nn = row0 + 16*r;
    float4 v = __ldg((const float4*)(in + (g*64+nn)*64 + c0));
    acc.x += fmaxf(fmaf(v.x,sc0,sh0),0.f);
    acc.y += fmaxf(fmaf(v.y,sc1,sh1),0.f);
    acc.z += fmaxf(fmaf(v.z,sc2,sh2),0.f);
    acc.w += fmaxf(fmaf(v.w,sc3,sh3),0.f);
  }
  *(float4*)(sp + row0*64 + c0) = acc;
  __syncthreads();
  if(t < 64){
    float s = 0.f;
    #pragma unroll
    for(int k=0;k<16;k++) s += sp[k*64 + t];
    out[g*64 + t] = s*(1.f/64.f);
  }
}

extern "C" void kernel_launch(void* const* d_in, const int* in_sizes, int n_in,
                              void* d_out, int out_size){
  const float* feat = (const float*)d_in[0];
  const int*   src  = (const int*)d_in[1];
  const float *c1w=(const float*)d_in[4],  *c1b=(const float*)d_in[5];
  const float *bn1g=(const float*)d_in[6], *bn1b=(const float*)d_in[7];
  const float *e1tw=(const float*)d_in[8], *e1tb=(const float*)d_in[9];
  const float *e1pw=(const float*)d_in[10],*e1pb=(const float*)d_in[11];
  const float *bne1g=(const float*)d_in[12],*bne1b=(const float*)d_in[13];
  const float *c2w=(const float*)d_in[14], *c2b=(const float*)d_in[15];
  const float *bn2g=(const float*)d_in[16],*bn2b=(const float*)d_in[17];
  const float *e2tw=(const float*)d_in[18],*e2tb=(const float*)d_in[19];
  const float *e2pw=(const float*)d_in[20],*e2pb=(const float*)d_in[21];
  const float *bne2g=(const float*)d_in[22],*bne2b=(const float*)d_in[23];
  const float *c3w=(const float*)d_in[24], *c3b=(const float*)d_in[25];
  const float *bn3g=(const float*)d_in[26],*bn3b=(const float*)d_in[27];
  float* out = (float*)d_out;

  const int SM1 = 11776*4;
  const int SMH = 17544*4;
  const int SME = 17864*4;
  cudaFuncSetAttribute(k_cheb1, cudaFuncAttributeMaxDynamicSharedMemorySize, SM1);
  cudaFuncSetAttribute(k_chebH, cudaFuncAttributeMaxDynamicSharedMemorySize, SMH);
  cudaFuncSetAttribute(k_econv, cudaFuncAttributeMaxDynamicSharedMemorySize, SME);

  float *bufA, *bufB;
  cudaGetSymbolAddress((void**)&bufA, g_bufA);
  cudaGetSymbolAddress((void**)&bufB, g_bufB);

  k_zero<<<1, 320>>>();
  k_cheb1<<<NG, 256, SM1>>>(feat, src, c1w, c1b);
  k_econv<<<NG, 256, SME>>>(e1tw, e1tb, e1pw, e1pb, 0, 1, bne1g, bne1b, src, bufA, bufB);
  k_chebH<<<NG, 256, SMH>>>(c2w, c2b, 1, 2, bn2g, bn2b, src, bufB, bufA);
  k_econv<<<NG, 256, SME>>>(e2tw, e2tb, e2pw, e2pb, 2, 3, bne2g, bne2b, src, bufA, bufB);
  k_chebH<<<NG, 256, SMH>>>(c3w, c3b, 3, 4, bn3g, bn3b, src, bufB, bufA);
  k_pool<<<NG, 256>>>(bn3g, bn3b, bufA, out);
}

// round 15
// speedup vs baseline: 2.7190x; 1.1004x over previous
#include <cuda_runtime.h>
#include <math.h>

#define NN   65536
#define NG   1024
#define PIT  68

typedef unsigned long long u64;

__device__ __align__(16) float g_bufA[NN*64];
__device__ __align__(16) float g_bufB[NN*64];
__device__ __align__(16) float g_sum[5][64];
__device__ __align__(16) float g_sq [5][64];

static __device__ __forceinline__ u64 f2fma(u64 a, u64 b, u64 c){
  u64 d; asm("fma.rn.f32x2 %0, %1, %2, %3;" : "=l"(d) : "l"(a), "l"(b), "l"(c)); return d;
}
static __device__ __forceinline__ u64 f2add(u64 a, u64 b){
  u64 d; asm("add.rn.f32x2 %0, %1, %2;" : "=l"(d) : "l"(a), "l"(b)); return d;
}
static __device__ __forceinline__ u64 f2mul(u64 a, u64 b){
  u64 d; asm("mul.rn.f32x2 %0, %1, %2;" : "=l"(d) : "l"(a), "l"(b)); return d;
}
static __device__ __forceinline__ u64 f2pack(float x, float y){
  u64 d; asm("mov.b64 %0, {%1,%2};" : "=l"(d) : "f"(x), "f"(y)); return d;
}
static __device__ __forceinline__ float f2lo(u64 a){ return __uint_as_float((unsigned)a); }
static __device__ __forceinline__ float f2hi(u64 a){ return __uint_as_float((unsigned)(a>>32)); }

static __device__ __forceinline__ float4 f4min(float4 a, float4 b){
  return make_float4(fminf(a.x,b.x),fminf(a.y,b.y),fminf(a.z,b.z),fminf(a.w,b.w));
}
static __device__ __forceinline__ float4 f4add(float4 a, float4 b){
  return make_float4(a.x+b.x,a.y+b.y,a.z+b.z,a.w+b.w);
}

// ---- balanced W-GEMM: out[dn+4i][cw+8r] += X[n][k].W[c][k], f32x2 over k ----
static __device__ __forceinline__ void bgemmW(u64 acc[4][4], const float* X, const float* W,
                                              int dn, int cw){
  #pragma unroll 2
  for(int ch=0;ch<16;ch++){
    ulonglong2 xv[4], wv[4];
    #pragma unroll
    for(int i=0;i<4;i++) xv[i] = *(const ulonglong2*)(X + (dn+4*i)*PIT + 4*ch);
    #pragma unroll
    for(int r=0;r<4;r++) wv[r] = *(const ulonglong2*)(W + (cw+8*r)*PIT + 4*ch);
    #pragma unroll
    for(int i=0;i<4;i++)
      #pragma unroll
      for(int r=0;r<4;r++){
        acc[i][r]=f2fma(xv[i].x, wv[r].x, acc[i][r]);
        acc[i][r]=f2fma(xv[i].y, wv[r].y, acc[i][r]);
      }
  }
}

// ---- per-CTA stats -> global channel accumulators (REDG, no fence) ----
static __device__ __forceinline__ void stats_atomic(const float* ys, float* pp, float* qq,
                                                    int t, int si){
  const int c = t & 63, qu = t >> 6;
  float s = 0.f, s2 = 0.f;
  #pragma unroll
  for(int k=0;k<16;k++){
    float v = ys[(qu*16+k)*PIT + c];
    s += v; s2 += v*v;
  }
  pp[qu*64+c] = s; qq[qu*64+c] = s2;
  __syncthreads();
  if(t < 64){
    atomicAdd(&g_sum[si][t], pp[t]+pp[t+64]+pp[t+128]+pp[t+192]);
    atomicAdd(&g_sq [si][t], qq[t]+qq[t+64]+qq[t+128]+qq[t+192]);
  }
}

// ---- reader head: compute scale/shift from accumulated stats ----
static __device__ __forceinline__ void bn_head(float* scs, float* shs, int t, int si,
                                               const float* __restrict__ gam,
                                               const float* __restrict__ bet){
  if(t < 64){
    float s1 = __ldcg(&g_sum[si][t]);
    float sq = __ldcg(&g_sq [si][t]);
    float mu  = s1*(1.f/(float)NN);
    float var = sq*(1.f/(float)NN) - mu*mu;
    float sc  = __ldg(gam+t) * rsqrtf(var + 1e-5f);
    scs[t] = sc; shs[t] = __ldg(bet+t) - mu*sc;
  }
}

__global__ void k_zero(){
  int i = threadIdx.x;
  if(i < 320){ ((float*)g_sum)[i] = 0.f; ((float*)g_sq)[i] = 0.f; }
}

// =============== cheb layer 1: feat (N,16) -> pre-BN (N,64) ===============
__global__ __launch_bounds__(256,3) void k_cheb1(const float* __restrict__ feat,
                                                 const int* __restrict__ src,
                                                 const float* __restrict__ w,
                                                 const float* __restrict__ b){
  extern __shared__ float sm[];
  float* xs = sm;            // 64*20
  float* x1 = sm + 1280;
  float* x2 = sm + 2560;
  float* wt = sm + 3840;     // pitch 52; free after GEMM -> stats scratch
  float* ys = sm + 7168;     // 64*68
  unsigned char* ls = (unsigned char*)(sm + 11520);
  const int g = blockIdx.x, t = threadIdx.x;

  for(int i=t;i<768;i+=256){
    int h = i & 63, kq = i >> 6;
    *(float4*)(wt + h*52 + 4*kq) = __ldg((const float4*)(w + h*48) + kq);
  }
  for(int i=t;i<256;i+=256){
    int nn = i>>2, j = i&3;
    *(float4*)(xs + nn*20 + 4*j) = __ldg((const float4*)(feat + (g*64+nn)*16) + j);
  }
  for(int i=t;i<1024;i+=256) ls[i] = (unsigned char)(__ldg(src + g*1024 + i) & 63);
  __syncthreads();

  const int n = t>>2, q = t&3, c0 = 4*q;
  const unsigned char* lr = ls + n*16;
  const u64 cm16 = f2pack(-0.0625f,-0.0625f);
  const u64 c125 = f2pack(0.125f,0.125f);
  const u64 cm1  = f2pack(-1.f,-1.f);
  { u64 A0=0,A1=0;
    #pragma unroll
    for(int j=0;j<16;j++){
      ulonglong2 r = *(const ulonglong2*)(xs + (int)lr[j]*20 + c0);
      A0 = f2add(A0, r.x); A1 = f2add(A1, r.y);
    }
    ulonglong2 o; o.x = f2mul(A0, cm16); o.y = f2mul(A1, cm16);
    *(ulonglong2*)(x1 + n*20 + c0) = o; }
  __syncthreads();
  { u64 A0=0,A1=0;
    #pragma unroll
    for(int j=0;j<16;j++){
      ulonglong2 r = *(const ulonglong2*)(x1 + (int)lr[j]*20 + c0);
      A0 = f2add(A0, r.x); A1 = f2add(A1, r.y);
    }
    ulonglong2 X0 = *(const ulonglong2*)(xs + n*20 + c0);
    ulonglong2 o;
    o.x = f2mul(f2fma(A0, c125, X0.x), cm1);
    o.y = f2mul(f2fma(A1, c125, X0.y), cm1);
    *(ulonglong2*)(x2 + n*20 + c0) = o; }
  __syncthreads();

  const int c4 = t & 15, n0 = (t>>4)*4;
  u64 acc[4][4];
  #pragma unroll
  for(int i=0;i<4;i++)
    #pragma unroll
    for(int j=0;j<4;j++) acc[i][j] = 0ull;
  const float* bufs[3] = {xs, x1, x2};
  #pragma unroll
  for(int seg=0;seg<3;seg++){
    const float* X = bufs[seg];
    #pragma unroll
    for(int ch=0;ch<4;ch++){
      ulonglong2 xv[4];
      #pragma unroll
      for(int i=0;i<4;i++) xv[i] = *(const ulonglong2*)(X + (n0+i)*20 + 4*ch);
      #pragma unroll
      for(int j=0;j<4;j++){
        ulonglong2 wv = *(const ulonglong2*)(wt + (c4+16*j)*52 + seg*16 + 4*ch);
        #pragma unroll
        for(int i=0;i<4;i++){
          acc[i][j] = f2fma(xv[i].x, wv.x, acc[i][j]);
          acc[i][j] = f2fma(xv[i].y, wv.y, acc[i][j]);
        }
      }
    }
  }
  __syncthreads();
  float bj[4];
  #pragma unroll
  for(int j=0;j<4;j++) bj[j] = __ldg(b + c4 + 16*j);
  float* obase = g_bufA + (g*64+n0)*64;
  #pragma unroll
  for(int i=0;i<4;i++)
    #pragma unroll
    for(int j=0;j<4;j++){
      float v = f2lo(acc[i][j]) + f2hi(acc[i][j]) + bj[j];
      ys[(n0+i)*PIT + c4 + 16*j] = v;
      obase[i*64 + c4 + 16*j] = v;
    }
  __syncthreads();
  stats_atomic(ys, wt, wt+256, t, 0);
}

// =============== cheb layers 2/3: laps via conflict-free gather ===============
// floats: xs 0  x1 4352  wt 8704  scs 13056  shs 13120  ls@13184 (1KB)
__global__ __launch_bounds__(256,3) void k_chebH(const float* __restrict__ w,
                                                 const float* __restrict__ b,
                                                 int si, int so,
                                                 const float* __restrict__ gam,
                                                 const float* __restrict__ bet,
                                                 const int* __restrict__ src,
                                                 const float* __restrict__ in,
                                                 float* __restrict__ out){
  extern __shared__ float sm[];
  float* xs  = sm;
  float* x1  = sm + 4352;
  float* wt  = sm + 8704;
  float* scs = sm + 13056;
  float* shs = sm + 13120;
  unsigned char* ls = (unsigned char*)(sm + 13184);
  float* ys  = x1;
  const int g = blockIdx.x, t = threadIdx.x;
  const int lane = t & 31, wp = t >> 5;
  const int dn = (wp>>1)*16 + (lane>>3);
  const int cw = (wp&1)*32 + (lane&7);
  const int half = lane >> 4;
  const int cl   = (lane & 15) * 4;
  const int wd0  = wp * 8;

  bn_head(scs, shs, t, si, gam, bet);
  for(int i=t;i<1024;i+=256){
    int nn=i>>4, j=i&15;
    *(float4*)(xs + nn*PIT + 4*j) = __ldg((const float4*)(in + (g*64+nn)*64) + j);
  }
  for(int i=t;i<1024;i+=256){
    int h=i&63, kq=i>>6;
    *(float4*)(wt + h*PIT + 4*kq) = __ldg((const float4*)(w + h*192) + kq);
  }
  for(int i=t;i<1024;i+=256) ls[i] = (unsigned char)(__ldg(src + g*1024 + i) & 63);
  __syncthreads();
  for(int i=t;i<1024;i+=256){
    int nn=i>>4, j=i&15, c=4*j;
    float4 v = *(float4*)(xs + nn*PIT + c);
    v.x=fmaxf(fmaf(v.x,scs[c+0],shs[c+0]),0.f);
    v.y=fmaxf(fmaf(v.y,scs[c+1],shs[c+1]),0.f);
    v.z=fmaxf(fmaf(v.z,scs[c+2],shs[c+2]),0.f);
    v.w=fmaxf(fmaf(v.w,scs[c+3],shs[c+3]),0.f);
    *(float4*)(xs + nn*PIT + c) = v;
  }
  __syncthreads();

  u64 aW[4][4];
  #pragma unroll
  for(int i=0;i<4;i++)
    #pragma unroll
    for(int r=0;r<4;r++) aW[i][r] = 0ull;

  // --- window 1: x1 = -(1/16) gather-sum(xs); GEMM0 on xs ---
  #pragma unroll 2
  for(int d = wd0; d < wd0 + 8; d++){
    uint4 lm = *(const uint4*)(ls + d*16);
    float4 s = make_float4(0.f,0.f,0.f,0.f);
    #pragma unroll
    for(int jj=0;jj<8;jj++){
      unsigned word = (jj>>1)==0 ? lm.x : (jj>>1)==1 ? lm.y : (jj>>1)==2 ? lm.z : lm.w;
      int sh = (((2*jj) & 3) + half) * 8;
      int row = (int)((word >> sh) & 63u);
      s = f4add(s, *(const float4*)(xs + row*PIT + cl));
    }
    s.x += __shfl_xor_sync(0xffffffffu, s.x, 16);
    s.y += __shfl_xor_sync(0xffffffffu, s.y, 16);
    s.z += __shfl_xor_sync(0xffffffffu, s.z, 16);
    s.w += __shfl_xor_sync(0xffffffffu, s.w, 16);
    if(half == 0)
      *(float4*)(x1 + d*PIT + cl) =
        make_float4(-0.0625f*s.x, -0.0625f*s.y, -0.0625f*s.z, -0.0625f*s.w);
  }
  bgemmW(aW, xs, wt, dn, cw);
  __syncthreads();

  // --- window 2: load W1; GEMM1 on x1; x2 = -(1/8) gather-sum(x1) - x0 -> xs ---
  for(int i=t;i<1024;i+=256){
    int h=i&63, kq=i>>6;
    *(float4*)(wt + h*PIT + 4*kq) = __ldg((const float4*)(w + h*192) + 16 + kq);
  }
  __syncthreads();
  bgemmW(aW, x1, wt, dn, cw);
  #pragma unroll 2
  for(int d = wd0; d < wd0 + 8; d++){
    uint4 lm = *(const uint4*)(ls + d*16);
    float4 s = make_float4(0.f,0.f,0.f,0.f);
    #pragma unroll
    for(int jj=0;jj<8;jj++){
      unsigned word = (jj>>1)==0 ? lm.x : (jj>>1)==1 ? lm.y : (jj>>1)==2 ? lm.z : lm.w;
      int sh = (((2*jj) & 3) + half) * 8;
      int row = (int)((word >> sh) & 63u);
      s = f4add(s, *(const float4*)(x1 + row*PIT + cl));
    }
    s.x += __shfl_xor_sync(0xffffffffu, s.x, 16);
    s.y += __shfl_xor_sync(0xffffffffu, s.y, 16);
    s.z += __shfl_xor_sync(0xffffffffu, s.z, 16);
    s.w += __shfl_xor_sync(0xffffffffu, s.w, 16);
    if(half == 0){
      float4 x0 = *(const float4*)(xs + d*PIT + cl);
      *(float4*)(xs + d*PIT + cl) =
        make_float4(-(0.125f*s.x + x0.x), -(0.125f*s.y + x0.y),
                    -(0.125f*s.z + x0.z), -(0.125f*s.w + x0.w));
    }
  }
  __syncthreads();

  // --- window 3: load W2; GEMM2 on xs(=x2) ---
  for(int i=t;i<1024;i+=256){
    int h=i&63, kq=i>>6;
    *(float4*)(wt + h*PIT + 4*kq) = __ldg((const float4*)(w + h*192) + 32 + kq);
  }
  __syncthreads();
  bgemmW(aW, xs, wt, dn, cw);
  __syncthreads();           // wt free; x1 (=ys) writable
  { float bj[4];
    #pragma unroll
    for(int r=0;r<4;r++) bj[r] = __ldg(b + cw + 8*r);
    #pragma unroll
    for(int i=0;i<4;i++)
      #pragma unroll
      for(int r=0;r<4;r++)
        ys[(dn+4*i)*PIT + cw + 8*r] = f2lo(aW[i][r]) + f2hi(aW[i][r]) + bj[r];
  }
  __syncthreads();
  for(int i=t;i<1024;i+=256){
    int nn=i>>4, j=i&15;
    *(float4*)(out + (g*64+nn)*64 + 4*j) = *(const float4*)(ys + nn*PIT + 4*j);
  }
  stats_atomic(ys, wt, wt+256, t, so);
}

// =============== edge conv: balanced GEMMs, conflict-free min ===============
__global__ __launch_bounds__(256,3) void k_econv(const float* __restrict__ tw,
                                                 const float* __restrict__ tb,
                                                 const float* __restrict__ pw,
                                                 const float* __restrict__ pb,
                                                 int si, int so,
                                                 const float* __restrict__ gam,
                                                 const float* __restrict__ bet,
                                                 const int* __restrict__ src,
                                                 const float* __restrict__ in,
                                                 float* __restrict__ out){
  extern __shared__ float sm[];
  float* xs  = sm;          float* psum = sm;
  float* wA  = sm + 4352;   float* ys   = sm + 4352;
  float* wB  = sm + 8704;   // free after pass 2 -> stats scratch
  float* ts  = sm + 13056;
  float* scs = sm + 17408;
  float* shs = sm + 17472;
  float* cbs = sm + 17536;
  unsigned char* ls = (unsigned char*)(sm + 17600);
  const int g = blockIdx.x, t = threadIdx.x;
  const int lane = t & 31, wp = t >> 5;
  const int dn = (wp>>1)*16 + (lane>>3);
  const int cw = (wp&1)*32 + (lane&7);

  bn_head(scs, shs, t, si, gam, bet);
  if(t < 64) cbs[t] = __ldg(tb+t)+__ldg(pb+t);
  for(int i=t;i<1024;i+=256){
    int h = i & 63, kq = i >> 6;
    *(float4*)(wA + h*PIT + 4*kq) = __ldg((const float4*)(tw + h*64) + kq);
    *(float4*)(wB + h*PIT + 4*kq) = __ldg((const float4*)(pw + h*64) + kq);
  }
  for(int i=t;i<1024;i+=256) ls[i] = (unsigned char)(__ldg(src + g*1024 + i) & 63);
  for(int i=t;i<1024;i+=256){
    int nn=i>>4, j=i&15;
    *(float4*)(xs + nn*PIT + 4*j) = __ldg((const float4*)(in + (g*64+nn)*64) + j);
  }
  __syncthreads();
  for(int i=t;i<1024;i+=256){
    int nn=i>>4, j=i&15, c=4*j;
    float4 v = *(float4*)(xs + nn*PIT + c);
    v.x=fmaxf(fmaf(v.x,scs[c+0],shs[c+0]),0.f);
    v.y=fmaxf(fmaf(v.y,scs[c+1],shs[c+1]),0.f);
    v.z=fmaxf(fmaf(v.z,scs[c+2],shs[c+2]),0.f);
    v.w=fmaxf(fmaf(v.w,scs[c+3],shs[c+3]),0.f);
    *(float4*)(xs + nn*PIT + c) = v;
  }
  __syncthreads();

  { u64 ta[4][4];
    #pragma unroll
    for(int i=0;i<4;i++)
      #pragma unroll
      for(int r=0;r<4;r++) ta[i][r]=0ull;
    bgemmW(ta, xs, wA, dn, cw);
    #pragma unroll
    for(int i=0;i<4;i++)
      #pragma unroll
      for(int r=0;r<4;r++)
        ts[(dn+4*i)*PIT + cw + 8*r] = f2lo(ta[i][r]) + f2hi(ta[i][r]);
  }
  u64 pa[4][4];
  #pragma unroll
  for(int i=0;i<4;i++)
    #pragma unroll
    for(int r=0;r<4;r++) pa[i][r]=0ull;
  bgemmW(pa, xs, wB, dn, cw);
  __syncthreads();
  #pragma unroll
  for(int i=0;i<4;i++)
    #pragma unroll
    for(int r=0;r<4;r++){
      int c = cw + 8*r, d = dn + 4*i;
      psum[d*PIT + c] = ts[d*PIT + c] + f2lo(pa[i][r]) + f2hi(pa[i][r]) + cbs[c];
    }
  __syncthreads();

  // min over neighbors: paired full-row reads, conflict-free by construction.
  const int half = lane >> 4;
  const int cl = (lane & 15) * 4;
  const int wd0 = wp * 8;
  #pragma unroll 2
  for(int d = wd0; d < wd0 + 8; d++){
    uint4 lm = *(const uint4*)(ls + d*16);
    float4 mn = make_float4(3e38f,3e38f,3e38f,3e38f);
    #pragma unroll
    for(int jj=0;jj<8;jj++){
      unsigned word = (jj>>1)==0 ? lm.x : (jj>>1)==1 ? lm.y : (jj>>1)==2 ? lm.z : lm.w;
      int sh = (((2*jj) & 3) + half) * 8;
      int row = (int)((word >> sh) & 63u);
      mn = f4min(mn, *(const float4*)(ts + row*PIT + cl));
    }
    mn.x = fminf(mn.x, __shfl_xor_sync(0xffffffffu, mn.x, 16));
    mn.y = fminf(mn.y, __shfl_xor_sync(0xffffffffu, mn.y, 16));
    mn.z = fminf(mn.z, __shfl_xor_sync(0xffffffffu, mn.z, 16));
    mn.w = fminf(mn.w, __shfl_xor_sync(0xffffffffu, mn.w, 16));
    if(half == 0){
      float4 p = *(const float4*)(psum + d*PIT + cl);
      float4 ov = make_float4(p.x-mn.x, p.y-mn.y, p.z-mn.z, p.w-mn.w);
      *(float4*)(ys + d*PIT + cl) = ov;
      *(float4*)(out + (g*64+d)*64 + cl) = ov;
    }
  }
  __syncthreads();
  stats_atomic(ys, wB, wB+256, t, so);
}

// ---------- final BN+ReLU + mean pool (coalesced, inline stats) ----------
__global__ __launch_bounds__(256) void k_pool(const float* __restrict__ gam,
                                              const float* __restrict__ bet,
                                              const float* __restrict__ in,
                                              float* __restrict__ out){
  __shared__ float sp[1024];
  __shared__ float scs[64], shs[64];
  const int g = blockIdx.x, t = threadIdx.x;
  bn_head(scs, shs, t, 4, gam, bet);
  __syncthreads();
  const int j = t & 15, row0 = t >> 4, c0 = 4*j;
  float sc0=scs[c0+0], sc1=scs[c0+1], sc2=scs[c0+2], sc3=scs[c0+3];
  float sh0=shs[c0+0], sh1=shs[c0+1], sh2=shs[c0+2], sh3=shs[c0+3];
  float4 acc = make_float4(0.f,0.f,0.f,0.f);
  #pragma unroll
  for(int r=0;r<4;r++){
    int nn = row0 + 16*r;
    float4 v = __ldg((const float4*)(in + (g*64+nn)*64 + c0));
    acc.x += fmaxf(fmaf(v.x,sc0,sh0),0.f);
    acc.y += fmaxf(fmaf(v.y,sc1,sh1),0.f);
    acc.z += fmaxf(fmaf(v.z,sc2,sh2),0.f);
    acc.w += fmaxf(fmaf(v.w,sc3,sh3),0.f);
  }
  *(float4*)(sp + row0*64 + c0) = acc;
  __syncthreads();
  if(t < 64){
    float s = 0.f;
    #pragma unroll
    for(int k=0;k<16;k++) s += sp[k*64 + t];
    out[g*64 + t] = s*(1.f/64.f);
  }
}

extern "C" void kernel_launch(void* const* d_in, const int* in_sizes, int n_in,
                              void* d_out, int out_size){
  const float* feat = (const float*)d_in[0];
  const int*   src  = (const int*)d_in[1];
  const float *c1w=(const float*)d_in[4],  *c1b=(const float*)d_in[5];
  const float *bn1g=(const float*)d_in[6], *bn1b=(const float*)d_in[7];
  const float *e1tw=(const float*)d_in[8], *e1tb=(const float*)d_in[9];
  const float *e1pw=(const float*)d_in[10],*e1pb=(const float*)d_in[11];
  const float *bne1g=(const float*)d_in[12],*bne1b=(const float*)d_in[13];
  const float *c2w=(const float*)d_in[14], *c2b=(const float*)d_in[15];
  const float *bn2g=(const float*)d_in[16],*bn2b=(const float*)d_in[17];
  const float *e2tw=(const float*)d_in[18],*e2tb=(const float*)d_in[19];
  const float *e2pw=(const float*)d_in[20],*e2pb=(const float*)d_in[21];
  const float *bne2g=(const float*)d_in[22],*bne2b=(const float*)d_in[23];
  const float *c3w=(const float*)d_in[24], *c3b=(const float*)d_in[25];
  const float *bn3g=(const float*)d_in[26],*bn3b=(const float*)d_in[27];
  float* out = (float*)d_out;

  const int SM1 = 11776*4;
  const int SMH = 13440*4;
  const int SME = 17864*4;
  cudaFuncSetAttribute(k_cheb1, cudaFuncAttributeMaxDynamicSharedMemorySize, SM1);
  cudaFuncSetAttribute(k_chebH, cudaFuncAttributeMaxDynamicSharedMemorySize, SMH);
  cudaFuncSetAttribute(k_econv, cudaFuncAttributeMaxDynamicSharedMemorySize, SME);

  float *bufA, *bufB;
  cudaGetSymbolAddress((void**)&bufA, g_bufA);
  cudaGetSymbolAddress((void**)&bufB, g_bufB);

  k_zero<<<1, 320>>>();
  k_cheb1<<<NG, 256, SM1>>>(feat, src, c1w, c1b);
  k_econv<<<NG, 256, SME>>>(e1tw, e1tb, e1pw, e1pb, 0, 1, bne1g, bne1b, src, bufA, bufB);
  k_chebH<<<NG, 256, SMH>>>(c2w, c2b, 1, 2, bn2g, bn2b, src, bufB, bufA);
  k_econv<<<NG, 256, SME>>>(e2tw, e2tb, e2pw, e2pb, 2, 3, bne2g, bne2b, src, bufA, bufB);
  k_chebH<<<NG, 256, SMH>>>(c3w, c3b, 3, 4, bn3g, bn3b, src, bufB, bufA);
  k_pool<<<NG, 256>>>(bn3g, bn3b, bufA, out);
}

// round 16
// speedup vs baseline: 2.7618x; 1.0157x over previous
#include <cuda_runtime.h>
#include <math.h>

#define NN   65536
#define NG   1024
#define PIT  68

typedef unsigned long long u64;

__device__ __align__(16) float g_bufA[NN*64];
__device__ __align__(16) float g_bufB[NN*64];
__device__ __align__(16) float g_sum[5][64];
__device__ __align__(16) float g_sq [5][64];

static __device__ __forceinline__ u64 f2fma(u64 a, u64 b, u64 c){
  u64 d; asm("fma.rn.f32x2 %0, %1, %2, %3;" : "=l"(d) : "l"(a), "l"(b), "l"(c)); return d;
}
static __device__ __forceinline__ u64 f2add(u64 a, u64 b){
  u64 d; asm("add.rn.f32x2 %0, %1, %2;" : "=l"(d) : "l"(a), "l"(b)); return d;
}
static __device__ __forceinline__ u64 f2mul(u64 a, u64 b){
  u64 d; asm("mul.rn.f32x2 %0, %1, %2;" : "=l"(d) : "l"(a), "l"(b)); return d;
}
static __device__ __forceinline__ u64 f2pack(float x, float y){
  u64 d; asm("mov.b64 %0, {%1,%2};" : "=l"(d) : "f"(x), "f"(y)); return d;
}
static __device__ __forceinline__ float f2lo(u64 a){ return __uint_as_float((unsigned)a); }
static __device__ __forceinline__ float f2hi(u64 a){ return __uint_as_float((unsigned)(a>>32)); }

static __device__ __forceinline__ float4 f4min(float4 a, float4 b){
  return make_float4(fminf(a.x,b.x),fminf(a.y,b.y),fminf(a.z,b.z),fminf(a.w,b.w));
}
static __device__ __forceinline__ float4 f4add(float4 a, float4 b){
  return make_float4(a.x+b.x,a.y+b.y,a.z+b.z,a.w+b.w);
}

// ---- balanced W-GEMM: out[dn+4i][cw+8r] += X[n][k].W[c][k], f32x2 over k ----
static __device__ __forceinline__ void bgemmW(u64 acc[4][4], const float* X, const float* W,
                                              int dn, int cw){
  #pragma unroll 2
  for(int ch=0;ch<16;ch++){
    ulonglong2 xv[4], wv[4];
    #pragma unroll
    for(int i=0;i<4;i++) xv[i] = *(const ulonglong2*)(X + (dn+4*i)*PIT + 4*ch);
    #pragma unroll
    for(int r=0;r<4;r++) wv[r] = *(const ulonglong2*)(W + (cw+8*r)*PIT + 4*ch);
    #pragma unroll
    for(int i=0;i<4;i++)
      #pragma unroll
      for(int r=0;r<4;r++){
        acc[i][r]=f2fma(xv[i].x, wv[r].x, acc[i][r]);
        acc[i][r]=f2fma(xv[i].y, wv[r].y, acc[i][r]);
      }
  }
}

// ---- per-CTA stats -> global channel accumulators (REDG, no fence) ----
static __device__ __forceinline__ void stats_atomic(const float* ys, float* pp, float* qq,
                                                    int t, int si){
  const int c = t & 63, qu = t >> 6;
  float s = 0.f, s2 = 0.f;
  #pragma unroll
  for(int k=0;k<16;k++){
    float v = ys[(qu*16+k)*PIT + c];
    s += v; s2 += v*v;
  }
  pp[qu*64+c] = s; qq[qu*64+c] = s2;
  __syncthreads();
  if(t < 64){
    atomicAdd(&g_sum[si][t], pp[t]+pp[t+64]+pp[t+128]+pp[t+192]);
    atomicAdd(&g_sq [si][t], qq[t]+qq[t+64]+qq[t+128]+qq[t+192]);
  }
}

// ---- reader head: compute scale/shift from accumulated stats ----
static __device__ __forceinline__ void bn_head(float* scs, float* shs, int t, int si,
                                               const float* __restrict__ gam,
                                               const float* __restrict__ bet){
  if(t < 64){
    float s1 = __ldcg(&g_sum[si][t]);
    float sq = __ldcg(&g_sq [si][t]);
    float mu  = s1*(1.f/(float)NN);
    float var = sq*(1.f/(float)NN) - mu*mu;
    float sc  = __ldg(gam+t) * rsqrtf(var + 1e-5f);
    scs[t] = sc; shs[t] = __ldg(bet+t) - mu*sc;
  }
}

__global__ void k_zero(){
  int i = threadIdx.x;
  if(i < 320){ ((float*)g_sum)[i] = 0.f; ((float*)g_sq)[i] = 0.f; }
}

// =============== cheb layer 1: feat (N,16) -> pre-BN (N,64) ===============
__global__ __launch_bounds__(256,3) void k_cheb1(const float* __restrict__ feat,
                                                 const int* __restrict__ src,
                                                 const float* __restrict__ w,
                                                 const float* __restrict__ b){
  extern __shared__ float sm[];
  float* xs = sm;            // 64*20
  float* x1 = sm + 1280;
  float* x2 = sm + 2560;
  float* wt = sm + 3840;     // pitch 52; free after GEMM -> stats scratch
  float* ys = sm + 7168;     // 64*68
  unsigned char* ls = (unsigned char*)(sm + 11520);
  const int g = blockIdx.x, t = threadIdx.x;

  for(int i=t;i<768;i+=256){
    int h = i & 63, kq = i >> 6;
    *(float4*)(wt + h*52 + 4*kq) = __ldg((const float4*)(w + h*48) + kq);
  }
  for(int i=t;i<256;i+=256){
    int nn = i>>2, j = i&3;
    *(float4*)(xs + nn*20 + 4*j) = __ldg((const float4*)(feat + (g*64+nn)*16) + j);
  }
  for(int i=t;i<1024;i+=256) ls[i] = (unsigned char)(__ldg(src + g*1024 + i) & 63);
  __syncthreads();

  const int n = t>>2, q = t&3, c0 = 4*q;
  const unsigned char* lr = ls + n*16;
  const u64 cm16 = f2pack(-0.0625f,-0.0625f);
  const u64 c125 = f2pack(0.125f,0.125f);
  const u64 cm1  = f2pack(-1.f,-1.f);
  { u64 A0=0,A1=0;
    #pragma unroll
    for(int j=0;j<16;j++){
      ulonglong2 r = *(const ulonglong2*)(xs + (int)lr[j]*20 + c0);
      A0 = f2add(A0, r.x); A1 = f2add(A1, r.y);
    }
    ulonglong2 o; o.x = f2mul(A0, cm16); o.y = f2mul(A1, cm16);
    *(ulonglong2*)(x1 + n*20 + c0) = o; }
  __syncthreads();
  { u64 A0=0,A1=0;
    #pragma unroll
    for(int j=0;j<16;j++){
      ulonglong2 r = *(const ulonglong2*)(x1 + (int)lr[j]*20 + c0);
      A0 = f2add(A0, r.x); A1 = f2add(A1, r.y);
    }
    ulonglong2 X0 = *(const ulonglong2*)(xs + n*20 + c0);
    ulonglong2 o;
    o.x = f2mul(f2fma(A0, c125, X0.x), cm1);
    o.y = f2mul(f2fma(A1, c125, X0.y), cm1);
    *(ulonglong2*)(x2 + n*20 + c0) = o; }
  __syncthreads();

  const int c4 = t & 15, n0 = (t>>4)*4;
  u64 acc[4][4];
  #pragma unroll
  for(int i=0;i<4;i++)
    #pragma unroll
    for(int j=0;j<4;j++) acc[i][j] = 0ull;
  const float* bufs[3] = {xs, x1, x2};
  #pragma unroll
  for(int seg=0;seg<3;seg++){
    const float* X = bufs[seg];
    #pragma unroll
    for(int ch=0;ch<4;ch++){
      ulonglong2 xv[4];
      #pragma unroll
      for(int i=0;i<4;i++) xv[i] = *(const ulonglong2*)(X + (n0+i)*20 + 4*ch);
      #pragma unroll
      for(int j=0;j<4;j++){
        ulonglong2 wv = *(const ulonglong2*)(wt + (c4+16*j)*52 + seg*16 + 4*ch);
        #pragma unroll
        for(int i=0;i<4;i++){
          acc[i][j] = f2fma(xv[i].x, wv.x, acc[i][j]);
          acc[i][j] = f2fma(xv[i].y, wv.y, acc[i][j]);
        }
      }
    }
  }
  __syncthreads();
  float bj[4];
  #pragma unroll
  for(int j=0;j<4;j++) bj[j] = __ldg(b + c4 + 16*j);
  float* obase = g_bufA + (g*64+n0)*64;
  #pragma unroll
  for(int i=0;i<4;i++)
    #pragma unroll
    for(int j=0;j<4;j++){
      float v = f2lo(acc[i][j]) + f2hi(acc[i][j]) + bj[j];
      ys[(n0+i)*PIT + c4 + 16*j] = v;
      obase[i*64 + c4 + 16*j] = v;
    }
  __syncthreads();
  stats_atomic(ys, wt, wt+256, t, 0);
}

// =============== cheb layers 2/3: double-buffered W, fused BN load ===============
// floats: xs 0  x1 4352  wtA 8704  wtB 13056  scs 17408  shs 17472  ls@17536
__global__ __launch_bounds__(256,3) void k_chebH(const float* __restrict__ w,
                                                 const float* __restrict__ b,
                                                 int si, int so,
                                                 const float* __restrict__ gam,
                                                 const float* __restrict__ bet,
                                                 const int* __restrict__ src,
                                                 const float* __restrict__ in,
                                                 float* __restrict__ out){
  extern __shared__ float sm[];
  float* xs  = sm;
  float* x1  = sm + 4352;
  float* wtA = sm + 8704;
  float* wtB = sm + 13056;
  float* scs = sm + 17408;
  float* shs = sm + 17472;
  unsigned char* ls = (unsigned char*)(sm + 17536);
  float* ys  = x1;
  const int g = blockIdx.x, t = threadIdx.x;
  const int lane = t & 31, wp = t >> 5;
  const int dn = (wp>>1)*16 + (lane>>3);
  const int cw = (wp&1)*32 + (lane&7);
  const int half = lane >> 4;
  const int cl   = (lane & 15) * 4;
  const int wd0  = wp * 8;

  bn_head(scs, shs, t, si, gam, bet);
  for(int i=t;i<1024;i+=256) ls[i] = (unsigned char)(__ldg(src + g*1024 + i) & 63);
  __syncthreads();

  // load x with BN+ReLU fused; load W0 -> wtA
  for(int i=t;i<1024;i+=256){
    int nn=i>>4, j=i&15, c=4*j;
    float4 v = __ldg((const float4*)(in + (g*64+nn)*64) + j);
    v.x=fmaxf(fmaf(v.x,scs[c+0],shs[c+0]),0.f);
    v.y=fmaxf(fmaf(v.y,scs[c+1],shs[c+1]),0.f);
    v.z=fmaxf(fmaf(v.z,scs[c+2],shs[c+2]),0.f);
    v.w=fmaxf(fmaf(v.w,scs[c+3],shs[c+3]),0.f);
    *(float4*)(xs + nn*PIT + c) = v;
  }
  for(int i=t;i<1024;i+=256){
    int h=i&63, kq=i>>6;
    *(float4*)(wtA + h*PIT + 4*kq) = __ldg((const float4*)(w + h*192) + kq);
  }
  __syncthreads();

  u64 aW[4][4];
  #pragma unroll
  for(int i=0;i<4;i++)
    #pragma unroll
    for(int r=0;r<4;r++) aW[i][r] = 0ull;

  // --- window 1: prefetch W1->wtB; x1 = -(1/16) gather-sum(xs); GEMM0(xs,wtA) ---
  for(int i=t;i<1024;i+=256){
    int h=i&63, kq=i>>6;
    *(float4*)(wtB + h*PIT + 4*kq) = __ldg((const float4*)(w + h*192) + 16 + kq);
  }
  #pragma unroll 2
  for(int d = wd0; d < wd0 + 8; d++){
    uint4 lm = *(const uint4*)(ls + d*16);
    float4 s = make_float4(0.f,0.f,0.f,0.f);
    #pragma unroll
    for(int jj=0;jj<8;jj++){
      unsigned word = (jj>>1)==0 ? lm.x : (jj>>1)==1 ? lm.y : (jj>>1)==2 ? lm.z : lm.w;
      int sh = (((2*jj) & 3) + half) * 8;
      int row = (int)((word >> sh) & 63u);
      s = f4add(s, *(const float4*)(xs + row*PIT + cl));
    }
    s.x += __shfl_xor_sync(0xffffffffu, s.x, 16);
    s.y += __shfl_xor_sync(0xffffffffu, s.y, 16);
    s.z += __shfl_xor_sync(0xffffffffu, s.z, 16);
    s.w += __shfl_xor_sync(0xffffffffu, s.w, 16);
    if(half == 0)
      *(float4*)(x1 + d*PIT + cl) =
        make_float4(-0.0625f*s.x, -0.0625f*s.y, -0.0625f*s.z, -0.0625f*s.w);
  }
  bgemmW(aW, xs, wtA, dn, cw);
  __syncthreads();

  // --- window 2: prefetch W2->wtA; GEMM1(x1,wtB); x2 = -(1/8) gather(x1) - x0 -> xs ---
  for(int i=t;i<1024;i+=256){
    int h=i&63, kq=i>>6;
    *(float4*)(wtA + h*PIT + 4*kq) = __ldg((const float4*)(w + h*192) + 32 + kq);
  }
  bgemmW(aW, x1, wtB, dn, cw);
  #pragma unroll 2
  for(int d = wd0; d < wd0 + 8; d++){
    uint4 lm = *(const uint4*)(ls + d*16);
    float4 s = make_float4(0.f,0.f,0.f,0.f);
    #pragma unroll
    for(int jj=0;jj<8;jj++){
      unsigned word = (jj>>1)==0 ? lm.x : (jj>>1)==1 ? lm.y : (jj>>1)==2 ? lm.z : lm.w;
      int sh = (((2*jj) & 3) + half) * 8;
      int row = (int)((word >> sh) & 63u);
      s = f4add(s, *(const float4*)(x1 + row*PIT + cl));
    }
    s.x += __shfl_xor_sync(0xffffffffu, s.x, 16);
    s.y += __shfl_xor_sync(0xffffffffu, s.y, 16);
    s.z += __shfl_xor_sync(0xffffffffu, s.z, 16);
    s.w += __shfl_xor_sync(0xffffffffu, s.w, 16);
    if(half == 0){
      float4 x0 = *(const float4*)(xs + d*PIT + cl);
      *(float4*)(xs + d*PIT + cl) =
        make_float4(-(0.125f*s.x + x0.x), -(0.125f*s.y + x0.y),
                    -(0.125f*s.z + x0.z), -(0.125f*s.w + x0.w));
    }
  }
  __syncthreads();

  // --- window 3: GEMM2(xs=x2, wtA) ---
  bgemmW(aW, xs, wtA, dn, cw);
  __syncthreads();           // x1 (=ys) writable
  { float bj[4];
    #pragma unroll
    for(int r=0;r<4;r++) bj[r] = __ldg(b + cw + 8*r);
    #pragma unroll
    for(int i=0;i<4;i++)
      #pragma unroll
      for(int r=0;r<4;r++)
        ys[(dn+4*i)*PIT + cw + 8*r] = f2lo(aW[i][r]) + f2hi(aW[i][r]) + bj[r];
  }
  __syncthreads();
  for(int i=t;i<1024;i+=256){
    int nn=i>>4, j=i&15;
    *(float4*)(out + (g*64+nn)*64 + 4*j) = *(const float4*)(ys + nn*PIT + 4*j);
  }
  stats_atomic(ys, wtB, wtB+256, t, so);
}

// =============== edge conv: balanced GEMMs, conflict-free min, fused BN load ===============
__global__ __launch_bounds__(256,3) void k_econv(const float* __restrict__ tw,
                                                 const float* __restrict__ tb,
                                                 const float* __restrict__ pw,
                                                 const float* __restrict__ pb,
                                                 int si, int so,
                                                 const float* __restrict__ gam,
                                                 const float* __restrict__ bet,
                                                 const int* __restrict__ src,
                                                 const float* __restrict__ in,
                                                 float* __restrict__ out){
  extern __shared__ float sm[];
  float* xs  = sm;          float* psum = sm;
  float* wA  = sm + 4352;   float* ys   = sm + 4352;
  float* wB  = sm + 8704;   // free after pass 2 -> stats scratch
  float* ts  = sm + 13056;
  float* scs = sm + 17408;
  float* shs = sm + 17472;
  float* cbs = sm + 17536;
  unsigned char* ls = (unsigned char*)(sm + 17600);
  const int g = blockIdx.x, t = threadIdx.x;
  const int lane = t & 31, wp = t >> 5;
  const int dn = (wp>>1)*16 + (lane>>3);
  const int cw = (wp&1)*32 + (lane&7);

  bn_head(scs, shs, t, si, gam, bet);
  if(t < 64) cbs[t] = __ldg(tb+t)+__ldg(pb+t);
  __syncthreads();
  for(int i=t;i<1024;i+=256){
    int h = i & 63, kq = i >> 6;
    *(float4*)(wA + h*PIT + 4*kq) = __ldg((const float4*)(tw + h*64) + kq);
    *(float4*)(wB + h*PIT + 4*kq) = __ldg((const float4*)(pw + h*64) + kq);
  }
  for(int i=t;i<1024;i+=256) ls[i] = (unsigned char)(__ldg(src + g*1024 + i) & 63);
  for(int i=t;i<1024;i+=256){
    int nn=i>>4, j=i&15, c=4*j;
    float4 v = __ldg((const float4*)(in + (g*64+nn)*64) + j);
    v.x=fmaxf(fmaf(v.x,scs[c+0],shs[c+0]),0.f);
    v.y=fmaxf(fmaf(v.y,scs[c+1],shs[c+1]),0.f);
    v.z=fmaxf(fmaf(v.z,scs[c+2],shs[c+2]),0.f);
    v.w=fmaxf(fmaf(v.w,scs[c+3],shs[c+3]),0.f);
    *(float4*)(xs + nn*PIT + c) = v;
  }
  __syncthreads();

  { u64 ta[4][4];
    #pragma unroll
    for(int i=0;i<4;i++)
      #pragma unroll
      for(int r=0;r<4;r++) ta[i][r]=0ull;
    bgemmW(ta, xs, wA, dn, cw);
    #pragma unroll
    for(int i=0;i<4;i++)
      #pragma unroll
      for(int r=0;r<4;r++)
        ts[(dn+4*i)*PIT + cw + 8*r] = f2lo(ta[i][r]) + f2hi(ta[i][r]);
  }
  u64 pa[4][4];
  #pragma unroll
  for(int i=0;i<4;i++)
    #pragma unroll
    for(int r=0;r<4;r++) pa[i][r]=0ull;
  bgemmW(pa, xs, wB, dn, cw);
  __syncthreads();
  #pragma unroll
  for(int i=0;i<4;i++)
    #pragma unroll
    for(int r=0;r<4;r++){
      int c = cw + 8*r, d = dn + 4*i;
      psum[d*PIT + c] = ts[d*PIT + c] + f2lo(pa[i][r]) + f2hi(pa[i][r]) + cbs[c];
    }
  __syncthreads();

  // min over neighbors: paired full-row reads, conflict-free by construction.
  const int half = lane >> 4;
  const int cl = (lane & 15) * 4;
  const int wd0 = wp * 8;
  #pragma unroll 2
  for(int d = wd0; d < wd0 + 8; d++){
    uint4 lm = *(const uint4*)(ls + d*16);
    float4 mn = make_float4(3e38f,3e38f,3e38f,3e38f);
    #pragma unroll
    for(int jj=0;jj<8;jj++){
      unsigned word = (jj>>1)==0 ? lm.x : (jj>>1)==1 ? lm.y : (jj>>1)==2 ? lm.z : lm.w;
      int sh = (((2*jj) & 3) + half) * 8;
      int row = (int)((word >> sh) & 63u);
      mn = f4min(mn, *(const float4*)(ts + row*PIT + cl));
    }
    mn.x = fminf(mn.x, __shfl_xor_sync(0xffffffffu, mn.x, 16));
    mn.y = fminf(mn.y, __shfl_xor_sync(0xffffffffu, mn.y, 16));
    mn.z = fminf(mn.z, __shfl_xor_sync(0xffffffffu, mn.z, 16));
    mn.w = fminf(mn.w, __shfl_xor_sync(0xffffffffu, mn.w, 16));
    if(half == 0){
      float4 p = *(const float4*)(psum + d*PIT + cl);
      float4 ov = make_float4(p.x-mn.x, p.y-mn.y, p.z-mn.z, p.w-mn.w);
      *(float4*)(ys + d*PIT + cl) = ov;
      *(float4*)(out + (g*64+d)*64 + cl) = ov;
    }
  }
  __syncthreads();
  stats_atomic(ys, wB, wB+256, t, so);
}

// ---------- final BN+ReLU + mean pool (coalesced, inline stats) ----------
__global__ __launch_bounds__(256) void k_pool(const float* __restrict__ gam,
                                              const float* __restrict__ bet,
                                              const float* __restrict__ in,
                                              float* __restrict__ out){
  __shared__ float sp[1024];
  __shared__ float scs[64], shs[64];
  const int g = blockIdx.x, t = threadIdx.x;
  bn_head(scs, shs, t, 4, gam, bet);
  __syncthreads();
  const int j = t & 15, row0 = t >> 4, c0 = 4*j;
  float sc0=scs[c0+0], sc1=scs[c0+1], sc2=scs[c0+2], sc3=scs[c0+3];
  float sh0=shs[c0+0], sh1=shs[c0+1], sh2=shs[c0+2], sh3=shs[c0+3];
  float4 acc = make_float4(0.f,0.f,0.f,0.f);
  #pragma unroll
  for(int r=0;r<4;r++){
    int nn = row0 + 16*r;
    float4 v = __ldg((const float4*)(in + (g*64+nn)*64 + c0));
    acc.x += fmaxf(fmaf(v.x,sc0,sh0),0.f);
    acc.y += fmaxf(fmaf(v.y,sc1,sh1),0.f);
    acc.z += fmaxf(fmaf(v.z,sc2,sh2),0.f);
    acc.w += fmaxf(fmaf(v.w,sc3,sh3),0.f);
  }
  *(float4*)(sp + row0*64 + c0) = acc;
  __syncthreads();
  if(t < 64){
    float s = 0.f;
    #pragma unroll
    for(int k=0;k<16;k++) s += sp[k*64 + t];
    out[g*64 + t] = s*(1.f/64.f);
  }
}

extern "C" void kernel_launch(void* const* d_in, const int* in_sizes, int n_in,
                              void* d_out, int out_size){
  const float* feat = (const float*)d_in[0];
  const int*   src  = (const int*)d_in[1];
  const float *c1w=(const float*)d_in[4],  *c1b=(const float*)d_in[5];
  const float *bn1g=(const float*)d_in[6], *bn1b=(const float*)d_in[7];
  const float *e1tw=(const float*)d_in[8], *e1tb=(const float*)d_in[9];
  const float *e1pw=(const float*)d_in[10],*e1pb=(const float*)d_in[11];
  const float *bne1g=(const float*)d_in[12],*bne1b=(const float*)d_in[13];
  const float *c2w=(const float*)d_in[14], *c2b=(const float*)d_in[15];
  const float *bn2g=(const float*)d_in[16],*bn2b=(const float*)d_in[17];
  const float *e2tw=(const float*)d_in[18],*e2tb=(const float*)d_in[19];
  const float *e2pw=(const float*)d_in[20],*e2pb=(const float*)d_in[21];
  const float *bne2g=(const float*)d_in[22],*bne2b=(const float*)d_in[23];
  const float *c3w=(const float*)d_in[24], *c3b=(const float*)d_in[25];
  const float *bn3g=(const float*)d_in[26],*bn3b=(const float*)d_in[27];
  float* out = (float*)d_out;

  const int SM1 = 11776*4;
  const int SMH = 17792*4;
  const int SME = 17864*4;
  cudaFuncSetAttribute(k_cheb1, cudaFuncAttributeMaxDynamicSharedMemorySize, SM1);
  cudaFuncSetAttribute(k_chebH, cudaFuncAttributeMaxDynamicSharedMemorySize, SMH);
  cudaFuncSetAttribute(k_econv, cudaFuncAttributeMaxDynamicSharedMemorySize, SME);

  float *bufA, *bufB;
  cudaGetSymbolAddress((void**)&bufA, g_bufA);
  cudaGetSymbolAddress((void**)&bufB, g_bufB);

  k_zero<<<1, 320>>>();
  k_cheb1<<<NG, 256, SM1>>>(feat, src, c1w, c1b);
  k_econv<<<NG, 256, SME>>>(e1tw, e1tb, e1pw, e1pb, 0, 1, bne1g, bne1b, src, bufA, bufB);
  k_chebH<<<NG, 256, SMH>>>(c2w, c2b, 1, 2, bn2g, bn2b, src, bufB, bufA);
  k_econv<<<NG, 256, SME>>>(e2tw, e2tb, e2pw, e2pb, 2, 3, bne2g, bne2b, src, bufA, bufB);
  k_chebH<<<NG, 256, SMH>>>(c3w, c3b, 3, 4, bn3g, bn3b, src, bufB, bufA);
  k_pool<<<NG, 256>>>(bn3g, bn3b, bufA, out);
}